// round 7
// baseline (speedup 1.0000x reference)
#include <cuda_runtime.h>
#include <math.h>

#define BB    16
#define CINN  64
#define COUTT 64
#define HH    256
#define WW    256
#define M1N   32
#define M2N   32
#define KXN   64   // rows 0..31 and 224..255

// ---------------- scratch (activations stay single-plane fp32) ----------------
__device__ float  g_Y1[BB * CINN * HH * 64];           // [b,i,h][2ky+t]  67MB
__device__ float2 g_Xf  [BB * CINN  * KXN * M2N];      // [b][i][kxi][ky]
__device__ float2 g_T   [BB * COUTT * KXN * M2N];
__device__ float2 g_OutF[BB * COUTT * KXN * M2N];
__device__ float  g_Z [BB * COUTT * HH * 64];          // [b,o][h][2ky+t] 67MB
// stationary matrices pre-split as float2(hi, lo)
__device__ float2 g_B1p[256 * 64];    // [w][2ky+t]        fwd W-DFT, scale 1/16
__device__ float2 g_A2p[128 * 512];   // [2kxi+t][2h+s]    fwd H-DFT, scale 1/16
__device__ float2 g_A5p[512 * 128];   // [2h+t][2kxi+s]    inv H-DFT
__device__ float2 g_C6p[64 * 256];    // [2ky+t][w]        inv W (irfft), scale 1/256

// ---------------- tf32 helpers ----------------
__device__ __forceinline__ unsigned tf32of(float x) {
    unsigned r; asm("cvt.rna.tf32.f32 %0,%1;" : "=r"(r) : "f"(x)); return r;
}
__device__ __forceinline__ void split2(float x, unsigned& h, unsigned& l) {
    h = tf32of(x);
    l = tf32of(x - __uint_as_float(h));
}
__device__ __forceinline__ float2 split2p(float x) {
    unsigned hu = tf32of(x);
    float hf = __uint_as_float(hu);
    return make_float2(hf, __uint_as_float(tf32of(x - hf)));
}
__device__ __forceinline__ unsigned B(float x) { return __float_as_uint(x); }

__device__ __forceinline__ void mma1(float* c, const unsigned* a, const unsigned* b) {
    asm volatile(
        "mma.sync.aligned.m16n8k8.row.col.f32.tf32.tf32.f32 "
        "{%0,%1,%2,%3},{%4,%5,%6,%7},{%8,%9},{%0,%1,%2,%3};"
        : "+f"(c[0]), "+f"(c[1]), "+f"(c[2]), "+f"(c[3])
        : "r"(a[0]), "r"(a[1]), "r"(a[2]), "r"(a[3]), "r"(b[0]), "r"(b[1]));
}
__device__ __forceinline__ void mma3(float* c, const unsigned* ah, const unsigned* al,
                                     const unsigned* bh, const unsigned* bl) {
    mma1(c, ah, bh);
    mma1(c, al, bh);
    mma1(c, ah, bl);
}

// ---------------- fill kernels (pre-split stationary matrices) ----------------
__global__ void __launch_bounds__(256) fill_B1() {
    int idx = blockIdx.x * 256 + threadIdx.x;           // 16384
    int w = idx >> 6, n = idx & 63, ky = n >> 1, t = n & 1;
    float s, c; sincospif((float)((w * ky) & 255) / 128.0f, &s, &c);
    g_B1p[idx] = split2p((t == 0 ? c : -s) * (1.0f / 16.0f));
}
__global__ void __launch_bounds__(256) fill_A2() {
    int idx = blockIdx.x * 256 + threadIdx.x;           // 65536
    int row = idx >> 9, col = idx & 511;
    int kxi = row >> 1, t = row & 1, h = col >> 1, s2 = col & 1;
    int kx = (kxi < 32) ? kxi : (192 + kxi);
    float s, c; sincospif((float)((kx * h) & 255) / 128.0f, &s, &c);
    float v = ((t == 0) ? ((s2 == 0) ? c : s) : ((s2 == 0) ? -s : c)) * (1.0f / 16.0f);
    g_A2p[idx] = split2p(v);
}
__global__ void __launch_bounds__(256) fill_A5() {
    int idx = blockIdx.x * 256 + threadIdx.x;           // 65536
    int row = idx >> 7, col = idx & 127;
    int h = row >> 1, t = row & 1, kxi = col >> 1, s2 = col & 1;
    int kx = (kxi < 32) ? kxi : (192 + kxi);
    float s, c; sincospif((float)((kx * h) & 255) / 128.0f, &s, &c);
    float v = (t == 0) ? ((s2 == 0) ? c : -s) : ((s2 == 0) ? s : c);
    g_A5p[idx] = split2p(v);
}
__global__ void __launch_bounds__(256) fill_C6() {
    int idx = blockIdx.x * 256 + threadIdx.x;           // 16384
    int k = idx >> 8, w = idx & 255;
    int ky = k >> 1, t = k & 1;
    float s, c; sincospif((float)((ky * w) & 255) / 128.0f, &s, &c);
    float base = ((ky == 0) ? 1.0f : 2.0f) * (1.0f / 256.0f);
    float v = (t == 0) ? base * c : ((ky == 0) ? 0.0f : -base * s);
    g_C6p[idx] = split2p(v);
}

// ---------------- S1: Y1 = x @ B1  (M=262144, K=256, N=64) ----------------
__global__ void __launch_bounds__(256, 2) s1_wdft(const float* __restrict__ x) {
    __shared__ float  sA[128][17];     // 8.7KB (x chunk, fp32)
    __shared__ float2 sB[16][65];      // 8.3KB (B1 chunk, pre-split pairs)
    const int tid = threadIdx.x, warp = tid >> 5, lane = tid & 31;
    const int g = lane >> 2, tg = lane & 3;
    const int r0 = blockIdx.x * 128;

    float c[8][4];
#pragma unroll
    for (int i = 0; i < 8; i++)
#pragma unroll
        for (int j = 0; j < 4; j++) c[i][j] = 0.f;

    for (int kc = 0; kc < 16; kc++) {
        __syncthreads();
        for (int i = tid; i < 128 * 16; i += 256) {
            int row = i >> 4, col = i & 15;
            sA[row][col] = x[(size_t)(r0 + row) * 256 + kc * 16 + col];
        }
        for (int i = tid; i < 16 * 64; i += 256) {
            int k = i >> 6, n = i & 63;
            sB[k][n] = g_B1p[(kc * 16 + k) * 64 + n];
        }
        __syncthreads();
#pragma unroll
        for (int ks = 0; ks < 2; ks++) {
            unsigned ah[4], al[4];
            split2(sA[warp * 16 + g    ][ks * 8 + tg    ], ah[0], al[0]);
            split2(sA[warp * 16 + g + 8][ks * 8 + tg    ], ah[1], al[1]);
            split2(sA[warp * 16 + g    ][ks * 8 + tg + 4], ah[2], al[2]);
            split2(sA[warp * 16 + g + 8][ks * 8 + tg + 4], ah[3], al[3]);
#pragma unroll
            for (int nt = 0; nt < 8; nt++) {
                float2 b0 = sB[ks * 8 + tg    ][nt * 8 + g];
                float2 b1 = sB[ks * 8 + tg + 4][nt * 8 + g];
                unsigned bh[2] = {B(b0.x), B(b1.x)};
                unsigned bl[2] = {B(b0.y), B(b1.y)};
                mma3(c[nt], ah, al, bh, bl);
            }
        }
    }
#pragma unroll
    for (int nt = 0; nt < 8; nt++) {
        int row = r0 + warp * 16 + g;
        int col = nt * 8 + 2 * tg;
        *(float2*)&g_Y1[(size_t)row * 64 + col]       = make_float2(c[nt][0], c[nt][1]);
        *(float2*)&g_Y1[(size_t)(row + 8) * 64 + col] = make_float2(c[nt][2], c[nt][3]);
    }
}

// ---------------- S2: Xf = A2 @ Y1slab  (per (b,i): M=128, K=512, N=32) ----------------
__global__ void __launch_bounds__(256, 2) s2_hdft() {
    __shared__ float2 sA[128][17];     // 17.4KB (A2 chunk, pre-split)
    __shared__ float2 sY[8][66];       // 4.2KB  (Y chunk, split at fill)
    const int tid = threadIdx.x, warp = tid >> 5, lane = tid & 31;
    const int g = lane >> 2, tg = lane & 3;
    const int bi = blockIdx.x;

    float c[4][4];
#pragma unroll
    for (int i = 0; i < 4; i++)
#pragma unroll
        for (int j = 0; j < 4; j++) c[i][j] = 0.f;

    for (int kc = 0; kc < 32; kc++) {        // chunks of 16 k (8 h-rows)
        __syncthreads();
        for (int i = tid; i < 128 * 16; i += 256) {
            int row = i >> 4, col = i & 15;
            sA[row][col] = g_A2p[row * 512 + kc * 16 + col];
        }
        for (int i = tid; i < 8 * 64; i += 256) {
            int h = i >> 6, cc = i & 63;
            sY[h][cc] = split2p(g_Y1[((size_t)bi * 256 + kc * 8 + h) * 64 + cc]);
        }
        __syncthreads();
#pragma unroll
        for (int ks = 0; ks < 2; ks++) {
            float2 a0 = sA[warp * 16 + g    ][ks * 8 + tg    ];
            float2 a1 = sA[warp * 16 + g + 8][ks * 8 + tg    ];
            float2 a2 = sA[warp * 16 + g    ][ks * 8 + tg + 4];
            float2 a3 = sA[warp * 16 + g + 8][ks * 8 + tg + 4];
            unsigned ah[4] = {B(a0.x), B(a1.x), B(a2.x), B(a3.x)};
            unsigned al[4] = {B(a0.y), B(a1.y), B(a2.y), B(a3.y)};
            int k0 = ks * 8 + tg, k1 = k0 + 4;
#pragma unroll
            for (int nt = 0; nt < 4; nt++) {
                int n = nt * 8 + g;
                float2 b0 = sY[k0 >> 1][2 * n + (k0 & 1)];
                float2 b1 = sY[k1 >> 1][2 * n + (k1 & 1)];
                unsigned bh[2] = {B(b0.x), B(b1.x)};
                unsigned bl[2] = {B(b0.y), B(b1.y)};
                mma3(c[nt], ah, al, bh, bl);
            }
        }
    }
    float* xf = (float*)g_Xf + (size_t)bi * 4096;
#pragma unroll
    for (int nt = 0; nt < 4; nt++) {
        int m0 = warp * 16 + g, m1 = m0 + 8;
        int n0 = nt * 8 + 2 * tg, n1 = n0 + 1;
        xf[(m0 >> 1) * 64 + 2 * n0 + (m0 & 1)] = c[nt][0];
        xf[(m0 >> 1) * 64 + 2 * n1 + (m0 & 1)] = c[nt][1];
        xf[(m1 >> 1) * 64 + 2 * n0 + (m1 & 1)] = c[nt][2];
        xf[(m1 >> 1) * 64 + 2 * n1 + (m1 & 1)] = c[nt][3];
    }
}

// ---------------- K3a (FFMA): t = sum_i Xf * w{1|2} ----------------
__global__ void __launch_bounds__(256) k3a_mixx(const float* __restrict__ wx1,
                                                const float* __restrict__ wx2) {
    __shared__ float2 sX[CINN][M2N];
    __shared__ float2 sW[CINN][COUTT];
    const int tid = threadIdx.x;
    const int kxi = blockIdx.x, b = blockIdx.y;
    const int m = (kxi < 32) ? kxi : (kxi - 32);
    const float2* wsrc = (const float2*)((kxi < 32) ? wx1 : wx2);

    for (int idx = tid; idx < CINN * M2N; idx += 256) {
        int i = idx >> 5, k = idx & 31;
        sX[i][k] = g_Xf[((b * CINN + i) * KXN + kxi) * M2N + k];
    }
    for (int idx = tid; idx < CINN * COUTT; idx += 256) {
        int i = idx >> 6, c = idx & 63;
        sW[i][c] = wsrc[(i * COUTT + c) * M1N + m];
    }
    __syncthreads();

    const int ky = tid & 31;
    const int cb = (tid >> 5) << 3;
    float2 acc[8];
#pragma unroll
    for (int j = 0; j < 8; j++) acc[j] = make_float2(0.f, 0.f);
    for (int i = 0; i < CINN; i++) {
        float2 xv = sX[i][ky];
#pragma unroll
        for (int j = 0; j < 8; j++) {
            float2 wv = sW[i][cb + j];
            acc[j].x = fmaf(xv.x, wv.x, fmaf(-xv.y, wv.y, acc[j].x));
            acc[j].y = fmaf(xv.x, wv.y, fmaf( xv.y, wv.x, acc[j].y));
        }
    }
#pragma unroll
    for (int j = 0; j < 8; j++)
        g_T[((b * COUTT + cb + j) * KXN + kxi) * M2N + ky] = acc[j];
}

// ---------------- K3b (FFMA): OutF = sum_c t * wy ----------------
__global__ void __launch_bounds__(256) k3b_mixy(const float* __restrict__ wy) {
    __shared__ float2 sT[32][KXN];
    __shared__ float2 sWy[32][COUTT];
    const int tid = threadIdx.x;
    const int ky = blockIdx.x, b = blockIdx.y;
    const int kxi = tid & 63;
    const int ob = (tid >> 6) << 4;
    const float2* wyp = (const float2*)wy;

    float2 acc[16];
#pragma unroll
    for (int j = 0; j < 16; j++) acc[j] = make_float2(0.f, 0.f);

    for (int cb = 0; cb < COUTT; cb += 32) {
        __syncthreads();
        for (int idx = tid; idx < 32 * KXN; idx += 256) {
            int cl = idx >> 6, kk = idx & 63;
            sT[cl][kk] = g_T[((b * COUTT + cb + cl) * KXN + kk) * M2N + ky];
        }
        for (int idx = tid; idx < 32 * COUTT; idx += 256) {
            int cl = idx >> 6, o = idx & 63;
            sWy[cl][o] = wyp[((cb + cl) * COUTT + o) * M2N + ky];
        }
        __syncthreads();
        for (int cl = 0; cl < 32; cl++) {
            float2 tv = sT[cl][kxi];
#pragma unroll
            for (int j = 0; j < 16; j++) {
                float2 wv = sWy[cl][ob + j];
                acc[j].x = fmaf(tv.x, wv.x, fmaf(-tv.y, wv.y, acc[j].x));
                acc[j].y = fmaf(tv.x, wv.y, fmaf( tv.y, wv.x, acc[j].y));
            }
        }
    }
#pragma unroll
    for (int j = 0; j < 16; j++)
        g_OutF[((b * COUTT + ob + j) * KXN + kxi) * M2N + ky] = acc[j];
}

// ---------------- S5: Z = A5 @ OutFslab  (per (b,o): M=512, K=128, N=32) ----------------
__global__ void __launch_bounds__(256, 2) s5_invh() {
    __shared__ float2 sA[256][9];      // 18.4KB (A5 chunk, pre-split)
    __shared__ float2 sF[4][66];       // 2.1KB  (OutF chunk, split at fill)
    const int tid = threadIdx.x, warp = tid >> 5, lane = tid & 31;
    const int g = lane >> 2, tg = lane & 3;
    const int mh = blockIdx.x, bo = blockIdx.y;

    const float* outf = (const float*)g_OutF + (size_t)bo * 4096;

    float c[2][4][4];
#pragma unroll
    for (int a = 0; a < 2; a++)
#pragma unroll
        for (int i = 0; i < 4; i++)
#pragma unroll
            for (int j = 0; j < 4; j++) c[a][i][j] = 0.f;

    for (int kc = 0; kc < 16; kc++) {        // chunks of 8 k (4 kxi rows)
        __syncthreads();
        for (int i = tid; i < 256 * 8; i += 256) {
            int row = i >> 3, col = i & 7;
            sA[row][col] = g_A5p[(mh * 256 + row) * 128 + kc * 8 + col];
        }
        for (int i = tid; i < 4 * 64; i += 256) {
            int r = i >> 6, cc = i & 63;
            sF[r][cc] = split2p(outf[(kc * 4 + r) * 64 + cc]);
        }
        __syncthreads();
        {
            unsigned bharr[4][2], blarr[4][2];
#pragma unroll
            for (int nt = 0; nt < 4; nt++) {
                int n = nt * 8 + g;
                float2 b0 = sF[tg >> 1      ][2 * n + (tg & 1)];
                float2 b1 = sF[(tg >> 1) + 2][2 * n + (tg & 1)];
                bharr[nt][0] = B(b0.x); bharr[nt][1] = B(b1.x);
                blarr[nt][0] = B(b0.y); blarr[nt][1] = B(b1.y);
            }
#pragma unroll
            for (int mt = 0; mt < 2; mt++) {
                int r = warp * 32 + mt * 16;
                float2 a0 = sA[r + g    ][tg    ];
                float2 a1 = sA[r + g + 8][tg    ];
                float2 a2 = sA[r + g    ][tg + 4];
                float2 a3 = sA[r + g + 8][tg + 4];
                unsigned ah[4] = {B(a0.x), B(a1.x), B(a2.x), B(a3.x)};
                unsigned al[4] = {B(a0.y), B(a1.y), B(a2.y), B(a3.y)};
#pragma unroll
                for (int nt = 0; nt < 4; nt++)
                    mma3(c[mt][nt], ah, al, bharr[nt], blarr[nt]);
            }
        }
    }
    float* z = g_Z + (size_t)bo * 16384;
#pragma unroll
    for (int mt = 0; mt < 2; mt++)
#pragma unroll
        for (int nt = 0; nt < 4; nt++) {
            int m0 = mh * 256 + warp * 32 + mt * 16 + g, m1 = m0 + 8;
            int n0 = nt * 8 + 2 * tg, n1 = n0 + 1;
            z[(m0 >> 1) * 64 + 2 * n0 + (m0 & 1)] = c[mt][nt][0];
            z[(m0 >> 1) * 64 + 2 * n1 + (m0 & 1)] = c[mt][nt][1];
            z[(m1 >> 1) * 64 + 2 * n0 + (m1 & 1)] = c[mt][nt][2];
            z[(m1 >> 1) * 64 + 2 * n1 + (m1 & 1)] = c[mt][nt][3];
        }
}

// ---------------- S6: out = Zslab @ C6  (per (b,o): M=256, K=64, N=256) ----------------
__global__ void __launch_bounds__(256, 2) s6_invw(float* __restrict__ out) {
    __shared__ float2 sZ[128][9];      // 9.2KB (Z chunk, split at fill)
    __shared__ float2 sC[8][129];      // 8.3KB (C6 chunk, pre-split)
    const int tid = threadIdx.x, warp = tid >> 5, lane = tid & 31;
    const int g = lane >> 2, tg = lane & 3;
    const int mt2 = blockIdx.x, nt2 = blockIdx.y, bo = blockIdx.z;

    float c[16][4];
#pragma unroll
    for (int i = 0; i < 16; i++)
#pragma unroll
        for (int j = 0; j < 4; j++) c[i][j] = 0.f;

    const float* z = g_Z + (size_t)bo * 16384;
    for (int kc = 0; kc < 8; kc++) {        // chunks of 8 k
        __syncthreads();
        for (int i = tid; i < 128 * 8; i += 256) {
            int row = i >> 3, col = i & 7;
            sZ[row][col] = split2p(z[(mt2 * 128 + row) * 64 + kc * 8 + col]);
        }
        for (int i = tid; i < 8 * 128; i += 256) {
            int k = i >> 7, n = i & 127;
            sC[k][n] = g_C6p[(kc * 8 + k) * 256 + nt2 * 128 + n];
        }
        __syncthreads();
        {
            float2 a0 = sZ[warp * 16 + g    ][tg    ];
            float2 a1 = sZ[warp * 16 + g + 8][tg    ];
            float2 a2 = sZ[warp * 16 + g    ][tg + 4];
            float2 a3 = sZ[warp * 16 + g + 8][tg + 4];
            unsigned ah[4] = {B(a0.x), B(a1.x), B(a2.x), B(a3.x)};
            unsigned al[4] = {B(a0.y), B(a1.y), B(a2.y), B(a3.y)};
#pragma unroll
            for (int nt = 0; nt < 16; nt++) {
                float2 b0 = sC[tg    ][nt * 8 + g];
                float2 b1 = sC[tg + 4][nt * 8 + g];
                unsigned bh[2] = {B(b0.x), B(b1.x)};
                unsigned bl[2] = {B(b0.y), B(b1.y)};
                mma3(c[nt], ah, al, bh, bl);
            }
        }
    }
    float* orow = out + (size_t)bo * 65536;
#pragma unroll
    for (int nt = 0; nt < 16; nt++) {
        int h = mt2 * 128 + warp * 16 + g;
        int w = nt2 * 128 + nt * 8 + 2 * tg;
        *(float2*)&orow[(h)     * 256 + w] = make_float2(c[nt][0], c[nt][1]);
        *(float2*)&orow[(h + 8) * 256 + w] = make_float2(c[nt][2], c[nt][3]);
    }
}

extern "C" void kernel_launch(void* const* d_in, const int* in_sizes, int n_in,
                              void* d_out, int out_size) {
    const float* x   = (const float*)d_in[0];
    const float* wx1 = (const float*)d_in[1];
    const float* wx2 = (const float*)d_in[2];
    const float* wy  = (const float*)d_in[3];
    float* out = (float*)d_out;

    fill_B1<<<64, 256>>>();
    fill_A2<<<256, 256>>>();
    fill_A5<<<256, 256>>>();
    fill_C6<<<64, 256>>>();

    s1_wdft<<<2048, 256>>>(x);                 // W-DFT
    s2_hdft<<<1024, 256>>>();                  // H-DFT
    k3a_mixx<<<dim3(KXN, BB), 256>>>(wx1, wx2);
    k3b_mixy<<<dim3(M2N, BB), 256>>>(wy);
    s5_invh<<<dim3(2, 1024), 256>>>();         // inverse H
    s6_invw<<<dim3(2, 2, 1024), 256>>>(out);   // inverse W (irfft)
}

// round 8
// speedup vs baseline: 1.1854x; 1.1854x over previous
#include <cuda_runtime.h>
#include <math.h>

#define BB    16
#define CINN  64
#define COUTT 64
#define HH    256
#define WW    256
#define M1N   32
#define M2N   32
#define KXN   64   // rows 0..31 and 224..255

// ---------------- scratch ----------------
__device__ float  g_Y1[BB * CINN * HH * 64];           // [b,i,h][2ky+t]  67MB
__device__ float2 g_Xf  [BB * CINN  * KXN * M2N];      // [b][i][kxi][ky]
__device__ float2 g_T   [BB * COUTT * KXN * M2N];
__device__ float2 g_OutF[BB * COUTT * KXN * M2N];
__device__ float  g_Z [BB * COUTT * HH * 64];          // [b,o][h][2ky+t] 67MB
// stationary matrices pre-split as float2(hi, lo)
__device__ float2 g_B1p[256 * 64];    // [w][2ky+t]        fwd W-DFT, scale 1/16
__device__ float2 g_A2p[128 * 512];   // [2kxi+t][2h+s]    fwd H-DFT, scale 1/16
__device__ float2 g_A5p[512 * 128];   // [2h+t][2kxi+s]    inv H-DFT
__device__ float2 g_C6p[64 * 256];    // [2ky+t][w]        inv W (irfft), scale 1/256

// ---------------- tf32 helpers ----------------
__device__ __forceinline__ unsigned tf32of(float x) {
    unsigned r; asm("cvt.rna.tf32.f32 %0,%1;" : "=r"(r) : "f"(x)); return r;
}
__device__ __forceinline__ void split2(float x, unsigned& h, unsigned& l) {
    h = tf32of(x);
    l = tf32of(x - __uint_as_float(h));
}
__device__ __forceinline__ float2 split2p(float x) {
    unsigned hu = tf32of(x);
    float hf = __uint_as_float(hu);
    return make_float2(hf, __uint_as_float(tf32of(x - hf)));
}
__device__ __forceinline__ unsigned B(float x) { return __float_as_uint(x); }

__device__ __forceinline__ void mma1(float* c, const unsigned* a, const unsigned* b) {
    asm volatile(
        "mma.sync.aligned.m16n8k8.row.col.f32.tf32.tf32.f32 "
        "{%0,%1,%2,%3},{%4,%5,%6,%7},{%8,%9},{%0,%1,%2,%3};"
        : "+f"(c[0]), "+f"(c[1]), "+f"(c[2]), "+f"(c[3])
        : "r"(a[0]), "r"(a[1]), "r"(a[2]), "r"(a[3]), "r"(b[0]), "r"(b[1]));
}
__device__ __forceinline__ void mma3(float* c, const unsigned* ah, const unsigned* al,
                                     const unsigned* bh, const unsigned* bl) {
    mma1(c, ah, bh);
    mma1(c, al, bh);
    mma1(c, ah, bl);
}

// ---------------- fill kernels ----------------
__global__ void __launch_bounds__(256) fill_B1() {
    int idx = blockIdx.x * 256 + threadIdx.x;           // 16384
    int w = idx >> 6, n = idx & 63, ky = n >> 1, t = n & 1;
    float s, c; sincospif((float)((w * ky) & 255) / 128.0f, &s, &c);
    g_B1p[idx] = split2p((t == 0 ? c : -s) * (1.0f / 16.0f));
}
__global__ void __launch_bounds__(256) fill_A2() {
    int idx = blockIdx.x * 256 + threadIdx.x;           // 65536
    int row = idx >> 9, col = idx & 511;
    int kxi = row >> 1, t = row & 1, h = col >> 1, s2 = col & 1;
    int kx = (kxi < 32) ? kxi : (192 + kxi);
    float s, c; sincospif((float)((kx * h) & 255) / 128.0f, &s, &c);
    float v = ((t == 0) ? ((s2 == 0) ? c : s) : ((s2 == 0) ? -s : c)) * (1.0f / 16.0f);
    g_A2p[idx] = split2p(v);
}
__global__ void __launch_bounds__(256) fill_A5() {
    int idx = blockIdx.x * 256 + threadIdx.x;           // 65536
    int row = idx >> 7, col = idx & 127;
    int h = row >> 1, t = row & 1, kxi = col >> 1, s2 = col & 1;
    int kx = (kxi < 32) ? kxi : (192 + kxi);
    float s, c; sincospif((float)((kx * h) & 255) / 128.0f, &s, &c);
    float v = (t == 0) ? ((s2 == 0) ? c : -s) : ((s2 == 0) ? s : c);
    g_A5p[idx] = split2p(v);
}
__global__ void __launch_bounds__(256) fill_C6() {
    int idx = blockIdx.x * 256 + threadIdx.x;           // 16384
    int k = idx >> 8, w = idx & 255;
    int ky = k >> 1, t = k & 1;
    float s, c; sincospif((float)((ky * w) & 255) / 128.0f, &s, &c);
    float base = ((ky == 0) ? 1.0f : 2.0f) * (1.0f / 256.0f);
    float v = (t == 0) ? base * c : ((ky == 0) ? 0.0f : -base * s);
    g_C6p[idx] = split2p(v);
}

// ---------------- S1: Y1 = x @ B1  (M=262144, K=256, N=64) — R4 chunking ----------------
__global__ void __launch_bounds__(256) s1_wdft(const float* __restrict__ x) {
    __shared__ float  sA[128][33];     // 16.9KB
    __shared__ float2 sB[32][65];      // 16.6KB pre-split pairs
    const int tid = threadIdx.x, warp = tid >> 5, lane = tid & 31;
    const int g = lane >> 2, tg = lane & 3;
    const int r0 = blockIdx.x * 128;

    float c[8][4];
#pragma unroll
    for (int i = 0; i < 8; i++)
#pragma unroll
        for (int j = 0; j < 4; j++) c[i][j] = 0.f;

    for (int kc = 0; kc < 8; kc++) {
        __syncthreads();
        for (int i = tid; i < 128 * 32; i += 256) {
            int row = i >> 5, col = i & 31;
            sA[row][col] = x[(size_t)(r0 + row) * 256 + kc * 32 + col];
        }
        for (int i = tid; i < 32 * 64; i += 256) {
            int k = i >> 6, n = i & 63;
            sB[k][n] = g_B1p[(kc * 32 + k) * 64 + n];
        }
        __syncthreads();
#pragma unroll
        for (int ks = 0; ks < 4; ks++) {
            unsigned ah[4], al[4];
            split2(sA[warp * 16 + g    ][ks * 8 + tg    ], ah[0], al[0]);
            split2(sA[warp * 16 + g + 8][ks * 8 + tg    ], ah[1], al[1]);
            split2(sA[warp * 16 + g    ][ks * 8 + tg + 4], ah[2], al[2]);
            split2(sA[warp * 16 + g + 8][ks * 8 + tg + 4], ah[3], al[3]);
#pragma unroll
            for (int nt = 0; nt < 8; nt++) {
                float2 b0 = sB[ks * 8 + tg    ][nt * 8 + g];
                float2 b1 = sB[ks * 8 + tg + 4][nt * 8 + g];
                unsigned bh[2] = {B(b0.x), B(b1.x)};
                unsigned bl[2] = {B(b0.y), B(b1.y)};
                mma3(c[nt], ah, al, bh, bl);
            }
        }
    }
#pragma unroll
    for (int nt = 0; nt < 8; nt++) {
        int row = r0 + warp * 16 + g;
        int col = nt * 8 + 2 * tg;
        *(float2*)&g_Y1[(size_t)row * 64 + col]       = make_float2(c[nt][0], c[nt][1]);
        *(float2*)&g_Y1[(size_t)(row + 8) * 64 + col] = make_float2(c[nt][2], c[nt][3]);
    }
}

// ---------------- S2: Xf = A2 @ Y1slab  (per (b,i): M=128, K=512, N=32) — R4 chunking ----------------
__global__ void __launch_bounds__(256) s2_hdft() {
    __shared__ float2 sA[128][33];     // 33.8KB pre-split
    __shared__ float2 sY[16][66];      // 8.4KB split at fill
    const int tid = threadIdx.x, warp = tid >> 5, lane = tid & 31;
    const int g = lane >> 2, tg = lane & 3;
    const int bi = blockIdx.x;

    float c[4][4];
#pragma unroll
    for (int i = 0; i < 4; i++)
#pragma unroll
        for (int j = 0; j < 4; j++) c[i][j] = 0.f;

    for (int kc = 0; kc < 16; kc++) {
        __syncthreads();
        for (int i = tid; i < 128 * 32; i += 256) {
            int row = i >> 5, col = i & 31;
            sA[row][col] = g_A2p[row * 512 + kc * 32 + col];
        }
        for (int i = tid; i < 16 * 64; i += 256) {
            int h = i >> 6, cc = i & 63;
            sY[h][cc] = split2p(g_Y1[((size_t)bi * 256 + kc * 16 + h) * 64 + cc]);
        }
        __syncthreads();
#pragma unroll
        for (int ks = 0; ks < 4; ks++) {
            float2 a0 = sA[warp * 16 + g    ][ks * 8 + tg    ];
            float2 a1 = sA[warp * 16 + g + 8][ks * 8 + tg    ];
            float2 a2 = sA[warp * 16 + g    ][ks * 8 + tg + 4];
            float2 a3 = sA[warp * 16 + g + 8][ks * 8 + tg + 4];
            unsigned ah[4] = {B(a0.x), B(a1.x), B(a2.x), B(a3.x)};
            unsigned al[4] = {B(a0.y), B(a1.y), B(a2.y), B(a3.y)};
            int k0 = ks * 8 + tg, k1 = k0 + 4;
#pragma unroll
            for (int nt = 0; nt < 4; nt++) {
                int n = nt * 8 + g;
                float2 b0 = sY[k0 >> 1][2 * n + (k0 & 1)];
                float2 b1 = sY[k1 >> 1][2 * n + (k1 & 1)];
                unsigned bh[2] = {B(b0.x), B(b1.x)};
                unsigned bl[2] = {B(b0.y), B(b1.y)};
                mma3(c[nt], ah, al, bh, bl);
            }
        }
    }
    float* xf = (float*)g_Xf + (size_t)bi * 4096;
#pragma unroll
    for (int nt = 0; nt < 4; nt++) {
        int m0 = warp * 16 + g, m1 = m0 + 8;
        int n0 = nt * 8 + 2 * tg, n1 = n0 + 1;
        xf[(m0 >> 1) * 64 + 2 * n0 + (m0 & 1)] = c[nt][0];
        xf[(m0 >> 1) * 64 + 2 * n1 + (m0 & 1)] = c[nt][1];
        xf[(m1 >> 1) * 64 + 2 * n0 + (m1 & 1)] = c[nt][2];
        xf[(m1 >> 1) * 64 + 2 * n1 + (m1 & 1)] = c[nt][3];
    }
}

// ---------------- K3a (FFMA, unchanged): t = sum_i Xf * w{1|2} ----------------
__global__ void __launch_bounds__(256) k3a_mixx(const float* __restrict__ wx1,
                                                const float* __restrict__ wx2) {
    __shared__ float2 sX[CINN][M2N];
    __shared__ float2 sW[CINN][COUTT];
    const int tid = threadIdx.x;
    const int kxi = blockIdx.x, b = blockIdx.y;
    const int m = (kxi < 32) ? kxi : (kxi - 32);
    const float2* wsrc = (const float2*)((kxi < 32) ? wx1 : wx2);

    for (int idx = tid; idx < CINN * M2N; idx += 256) {
        int i = idx >> 5, k = idx & 31;
        sX[i][k] = g_Xf[((b * CINN + i) * KXN + kxi) * M2N + k];
    }
    for (int idx = tid; idx < CINN * COUTT; idx += 256) {
        int i = idx >> 6, c = idx & 63;
        sW[i][c] = wsrc[(i * COUTT + c) * M1N + m];
    }
    __syncthreads();

    const int ky = tid & 31;
    const int cb = (tid >> 5) << 3;
    float2 acc[8];
#pragma unroll
    for (int j = 0; j < 8; j++) acc[j] = make_float2(0.f, 0.f);
    for (int i = 0; i < CINN; i++) {
        float2 xv = sX[i][ky];
#pragma unroll
        for (int j = 0; j < 8; j++) {
            float2 wv = sW[i][cb + j];
            acc[j].x = fmaf(xv.x, wv.x, fmaf(-xv.y, wv.y, acc[j].x));
            acc[j].y = fmaf(xv.x, wv.y, fmaf( xv.y, wv.x, acc[j].y));
        }
    }
#pragma unroll
    for (int j = 0; j < 8; j++)
        g_T[((b * COUTT + cb + j) * KXN + kxi) * M2N + ky] = acc[j];
}

// ---------------- K3b (FFMA, unchanged): OutF = sum_c t * wy ----------------
__global__ void __launch_bounds__(256) k3b_mixy(const float* __restrict__ wy) {
    __shared__ float2 sT[32][KXN];
    __shared__ float2 sWy[32][COUTT];
    const int tid = threadIdx.x;
    const int ky = blockIdx.x, b = blockIdx.y;
    const int kxi = tid & 63;
    const int ob = (tid >> 6) << 4;
    const float2* wyp = (const float2*)wy;

    float2 acc[16];
#pragma unroll
    for (int j = 0; j < 16; j++) acc[j] = make_float2(0.f, 0.f);

    for (int cb = 0; cb < COUTT; cb += 32) {
        __syncthreads();
        for (int idx = tid; idx < 32 * KXN; idx += 256) {
            int cl = idx >> 6, kk = idx & 63;
            sT[cl][kk] = g_T[((b * COUTT + cb + cl) * KXN + kk) * M2N + ky];
        }
        for (int idx = tid; idx < 32 * COUTT; idx += 256) {
            int cl = idx >> 6, o = idx & 63;
            sWy[cl][o] = wyp[((cb + cl) * COUTT + o) * M2N + ky];
        }
        __syncthreads();
        for (int cl = 0; cl < 32; cl++) {
            float2 tv = sT[cl][kxi];
#pragma unroll
            for (int j = 0; j < 16; j++) {
                float2 wv = sWy[cl][ob + j];
                acc[j].x = fmaf(tv.x, wv.x, fmaf(-tv.y, wv.y, acc[j].x));
                acc[j].y = fmaf(tv.x, wv.y, fmaf( tv.y, wv.x, acc[j].y));
            }
        }
    }
#pragma unroll
    for (int j = 0; j < 16; j++)
        g_OutF[((b * COUTT + ob + j) * KXN + kxi) * M2N + ky] = acc[j];
}

// ---------------- S5: Z = A5 @ OutFslab  (per (b,o): M=512, K=128, N=32) — R4 chunking ----------------
__global__ void __launch_bounds__(256) s5_invh() {
    __shared__ float2 sA[256][17];     // 34.8KB pre-split
    __shared__ float2 sF[8][66];       // 4.2KB split at fill (per-chunk rows)
    const int tid = threadIdx.x, warp = tid >> 5, lane = tid & 31;
    const int g = lane >> 2, tg = lane & 3;
    const int mh = blockIdx.x, bo = blockIdx.y;

    const float* outf = (const float*)g_OutF + (size_t)bo * 4096;

    float c[2][4][4];
#pragma unroll
    for (int a = 0; a < 2; a++)
#pragma unroll
        for (int i = 0; i < 4; i++)
#pragma unroll
            for (int j = 0; j < 4; j++) c[a][i][j] = 0.f;

    for (int kc = 0; kc < 8; kc++) {       // 16 k per chunk (as R4)
        __syncthreads();
        for (int i = tid; i < 256 * 16; i += 256) {
            int row = i >> 4, col = i & 15;
            sA[row][col] = g_A5p[(mh * 256 + row) * 128 + kc * 16 + col];
        }
        for (int i = tid; i < 8 * 64; i += 256) {
            int r = i >> 6, cc = i & 63;
            sF[r][cc] = split2p(outf[(kc * 8 + r) * 64 + cc]);
        }
        __syncthreads();
#pragma unroll
        for (int ks = 0; ks < 2; ks++) {
            int l0 = (ks * 8 + tg) >> 1, l1 = (ks * 8 + tg + 4) >> 1;
            int par = tg & 1;
            unsigned bharr[4][2], blarr[4][2];
#pragma unroll
            for (int nt = 0; nt < 4; nt++) {
                int n = nt * 8 + g;
                float2 b0 = sF[l0][2 * n + par];
                float2 b1 = sF[l1][2 * n + par];
                bharr[nt][0] = B(b0.x); bharr[nt][1] = B(b1.x);
                blarr[nt][0] = B(b0.y); blarr[nt][1] = B(b1.y);
            }
#pragma unroll
            for (int mt = 0; mt < 2; mt++) {
                int r = warp * 32 + mt * 16;
                float2 a0 = sA[r + g    ][ks * 8 + tg    ];
                float2 a1 = sA[r + g + 8][ks * 8 + tg    ];
                float2 a2 = sA[r + g    ][ks * 8 + tg + 4];
                float2 a3 = sA[r + g + 8][ks * 8 + tg + 4];
                unsigned ah[4] = {B(a0.x), B(a1.x), B(a2.x), B(a3.x)};
                unsigned al[4] = {B(a0.y), B(a1.y), B(a2.y), B(a3.y)};
#pragma unroll
                for (int nt = 0; nt < 4; nt++)
                    mma3(c[mt][nt], ah, al, bharr[nt], blarr[nt]);
            }
        }
    }
    float* z = g_Z + (size_t)bo * 16384;
#pragma unroll
    for (int mt = 0; mt < 2; mt++)
#pragma unroll
        for (int nt = 0; nt < 4; nt++) {
            int m0 = mh * 256 + warp * 32 + mt * 16 + g, m1 = m0 + 8;
            int n0 = nt * 8 + 2 * tg, n1 = n0 + 1;
            z[(m0 >> 1) * 64 + 2 * n0 + (m0 & 1)] = c[mt][nt][0];
            z[(m0 >> 1) * 64 + 2 * n1 + (m0 & 1)] = c[mt][nt][1];
            z[(m1 >> 1) * 64 + 2 * n0 + (m1 & 1)] = c[mt][nt][2];
            z[(m1 >> 1) * 64 + 2 * n1 + (m1 & 1)] = c[mt][nt][3];
        }
}

// ---------------- S6: out = Zslab @ C6  (per (b,o): M=256, K=64, N=256) ----------------
__global__ void __launch_bounds__(256) s6_invw(float* __restrict__ out) {
    __shared__ float2 sZ[128][17];     // 17.4KB split at fill
    __shared__ float2 sC[16][129];     // 16.5KB pre-split
    const int tid = threadIdx.x, warp = tid >> 5, lane = tid & 31;
    const int g = lane >> 2, tg = lane & 3;
    const int mt2 = blockIdx.x, nt2 = blockIdx.y, bo = blockIdx.z;

    float c[16][4];
#pragma unroll
    for (int i = 0; i < 16; i++)
#pragma unroll
        for (int j = 0; j < 4; j++) c[i][j] = 0.f;

    const float* z = g_Z + (size_t)bo * 16384;
    for (int kc = 0; kc < 4; kc++) {        // 16 k per chunk
        __syncthreads();
        for (int i = tid; i < 128 * 16; i += 256) {
            int row = i >> 4, col = i & 15;
            sZ[row][col] = split2p(z[(mt2 * 128 + row) * 64 + kc * 16 + col]);
        }
        for (int i = tid; i < 16 * 128; i += 256) {
            int k = i >> 7, n = i & 127;
            sC[k][n] = g_C6p[(kc * 16 + k) * 256 + nt2 * 128 + n];
        }
        __syncthreads();
#pragma unroll
        for (int ks = 0; ks < 2; ks++) {
            float2 a0 = sZ[warp * 16 + g    ][ks * 8 + tg    ];
            float2 a1 = sZ[warp * 16 + g + 8][ks * 8 + tg    ];
            float2 a2 = sZ[warp * 16 + g    ][ks * 8 + tg + 4];
            float2 a3 = sZ[warp * 16 + g + 8][ks * 8 + tg + 4];
            unsigned ah[4] = {B(a0.x), B(a1.x), B(a2.x), B(a3.x)};
            unsigned al[4] = {B(a0.y), B(a1.y), B(a2.y), B(a3.y)};
#pragma unroll
            for (int nt = 0; nt < 16; nt++) {
                float2 b0 = sC[ks * 8 + tg    ][nt * 8 + g];
                float2 b1 = sC[ks * 8 + tg + 4][nt * 8 + g];
                unsigned bh[2] = {B(b0.x), B(b1.x)};
                unsigned bl[2] = {B(b0.y), B(b1.y)};
                mma3(c[nt], ah, al, bh, bl);
            }
        }
    }
    float* orow = out + (size_t)bo * 65536;
#pragma unroll
    for (int nt = 0; nt < 16; nt++) {
        int h = mt2 * 128 + warp * 16 + g;
        int w = nt2 * 128 + nt * 8 + 2 * tg;
        *(float2*)&orow[(h)     * 256 + w] = make_float2(c[nt][0], c[nt][1]);
        *(float2*)&orow[(h + 8) * 256 + w] = make_float2(c[nt][2], c[nt][3]);
    }
}

extern "C" void kernel_launch(void* const* d_in, const int* in_sizes, int n_in,
                              void* d_out, int out_size) {
    const float* x   = (const float*)d_in[0];
    const float* wx1 = (const float*)d_in[1];
    const float* wx2 = (const float*)d_in[2];
    const float* wy  = (const float*)d_in[3];
    float* out = (float*)d_out;

    fill_B1<<<64, 256>>>();
    fill_A2<<<256, 256>>>();
    fill_A5<<<256, 256>>>();
    fill_C6<<<64, 256>>>();

    s1_wdft<<<2048, 256>>>(x);                 // W-DFT
    s2_hdft<<<1024, 256>>>();                  // H-DFT
    k3a_mixx<<<dim3(KXN, BB), 256>>>(wx1, wx2);
    k3b_mixy<<<dim3(M2N, BB), 256>>>(wy);
    s5_invh<<<dim3(2, 1024), 256>>>();         // inverse H
    s6_invw<<<dim3(2, 2, 1024), 256>>>(out);   // inverse W (irfft)
}

// round 9
// speedup vs baseline: 1.5841x; 1.3363x over previous
#include <cuda_runtime.h>
#include <math.h>

#define BB    16
#define CINN  64
#define COUTT 64
#define HH    256
#define WW    256
#define M1N   32
#define M2N   32
#define KXN   64   // rows 0..31 and 224..255

// ---------------- scratch ----------------
__device__ float2 g_Xf  [BB * CINN  * KXN * M2N];      // [b][i][kxi][ky]
__device__ float2 g_T   [BB * COUTT * KXN * M2N];
__device__ float2 g_OutF[BB * COUTT * KXN * M2N];
// stationary matrices (plain fp32, split per use — R4 format)
__device__ float g_B1[256 * 64];    // [w][2ky+t]          fwd W-DFT, scale 1/16
__device__ float g_A2[128 * 512];   // [2kxi+t][2h+s]      fwd H-DFT, scale 1/16
__device__ float g_A5[512 * 128];   // [2h+t][2kxi+s]      inv H-DFT
__device__ float g_C6[64 * 256];    // [2ky+t][w]          inv W (irfft), scale 1/256

// ---------------- tf32 mma helpers ----------------
__device__ __forceinline__ unsigned tf32of(float x) {
    unsigned r; asm("cvt.rna.tf32.f32 %0,%1;" : "=r"(r) : "f"(x)); return r;
}
__device__ __forceinline__ void split2(float x, unsigned& h, unsigned& l) {
    h = tf32of(x);
    l = tf32of(x - __uint_as_float(h));
}
__device__ __forceinline__ void mma1(float* c, const unsigned* a, const unsigned* b) {
    asm volatile(
        "mma.sync.aligned.m16n8k8.row.col.f32.tf32.tf32.f32 "
        "{%0,%1,%2,%3},{%4,%5,%6,%7},{%8,%9},{%0,%1,%2,%3};"
        : "+f"(c[0]), "+f"(c[1]), "+f"(c[2]), "+f"(c[3])
        : "r"(a[0]), "r"(a[1]), "r"(a[2]), "r"(a[3]), "r"(b[0]), "r"(b[1]));
}
__device__ __forceinline__ void mma3(float* c, const unsigned* ah, const unsigned* al,
                                     const unsigned* bh, const unsigned* bl) {
    mma1(c, ah, bh);
    mma1(c, al, bh);
    mma1(c, ah, bl);
}

// ---------------- single fill kernel ----------------
__global__ void __launch_bounds__(256) fill_all() {
    int idx = blockIdx.x * 256 + threadIdx.x;           // 65536 threads
    // A2 [128][512]
    {
        int row = idx >> 9, col = idx & 511;
        int kxi = row >> 1, t = row & 1, h = col >> 1, s2 = col & 1;
        int kx = (kxi < 32) ? kxi : (192 + kxi);
        float s, c; sincospif((float)((kx * h) & 255) / 128.0f, &s, &c);
        float v = ((t == 0) ? ((s2 == 0) ? c : s) : ((s2 == 0) ? -s : c)) * (1.0f / 16.0f);
        g_A2[idx] = v;
    }
    // A5 [512][128]
    {
        int row = idx >> 7, col = idx & 127;
        int h = row >> 1, t = row & 1, kxi = col >> 1, s2 = col & 1;
        int kx = (kxi < 32) ? kxi : (192 + kxi);
        float s, c; sincospif((float)((kx * h) & 255) / 128.0f, &s, &c);
        g_A5[idx] = (t == 0) ? ((s2 == 0) ? c : -s) : ((s2 == 0) ? s : c);
    }
    if (idx < 16384) {
        // B1 [256][64]
        {
            int w = idx >> 6, n = idx & 63, ky = n >> 1, t = n & 1;
            float s, c; sincospif((float)((w * ky) & 255) / 128.0f, &s, &c);
            g_B1[idx] = (t == 0 ? c : -s) * (1.0f / 16.0f);
        }
        // C6 [64][256]
        {
            int k = idx >> 8, w = idx & 255;
            int ky = k >> 1, t = k & 1;
            float s, c; sincospif((float)((ky * w) & 255) / 128.0f, &s, &c);
            float base = ((ky == 0) ? 1.0f : 2.0f) * (1.0f / 256.0f);
            g_C6[idx] = (t == 0) ? base * c : ((ky == 0) ? 0.0f : -base * s);
        }
    }
}

// ---------------- S12 fused: per (b,i): Y = x @ B1 in smem, then Xf = A2 @ Y ----------------
// dyn smem: sY[256][66] | sA[128][33] | sB[32][65]
#define S12_SY  (256 * 66)
#define S12_SA  (128 * 33)
#define S12_SB  (32 * 65)
#define S12_SMEM ((S12_SY + S12_SA + S12_SB) * 4)

__global__ void __launch_bounds__(256) s12_fused(const float* __restrict__ x) {
    extern __shared__ float sm[];
    float* sY = sm;                 // [256][66]
    float* sA = sm + S12_SY;        // [128][33]
    float* sB = sA + S12_SA;        // [32][65]
    const int tid = threadIdx.x, warp = tid >> 5, lane = tid & 31;
    const int g = lane >> 2, tg = lane & 3;
    const int bi = blockIdx.x;
    const float* xs = x + (size_t)bi * 65536;

    // ---- GEMM1: Y = x @ B1, two M=128 halves (R4-s1 body) ----
    for (int half = 0; half < 2; half++) {
        float c[8][4];
#pragma unroll
        for (int i = 0; i < 8; i++)
#pragma unroll
            for (int j = 0; j < 4; j++) c[i][j] = 0.f;

        for (int kc = 0; kc < 8; kc++) {
            __syncthreads();
            for (int i = tid; i < 128 * 32; i += 256) {
                int row = i >> 5, col = i & 31;
                sA[row * 33 + col] = xs[(size_t)(half * 128 + row) * 256 + kc * 32 + col];
            }
            for (int i = tid; i < 32 * 64; i += 256) {
                int k = i >> 6, n = i & 63;
                sB[k * 65 + n] = g_B1[(kc * 32 + k) * 64 + n];
            }
            __syncthreads();
#pragma unroll
            for (int ks = 0; ks < 4; ks++) {
                unsigned ah[4], al[4];
                split2(sA[(warp * 16 + g    ) * 33 + ks * 8 + tg    ], ah[0], al[0]);
                split2(sA[(warp * 16 + g + 8) * 33 + ks * 8 + tg    ], ah[1], al[1]);
                split2(sA[(warp * 16 + g    ) * 33 + ks * 8 + tg + 4], ah[2], al[2]);
                split2(sA[(warp * 16 + g + 8) * 33 + ks * 8 + tg + 4], ah[3], al[3]);
#pragma unroll
                for (int nt = 0; nt < 8; nt++) {
                    unsigned bh[2], bl[2];
                    split2(sB[(ks * 8 + tg    ) * 65 + nt * 8 + g], bh[0], bl[0]);
                    split2(sB[(ks * 8 + tg + 4) * 65 + nt * 8 + g], bh[1], bl[1]);
                    mma3(c[nt], ah, al, bh, bl);
                }
            }
        }
#pragma unroll
        for (int nt = 0; nt < 8; nt++) {
            int row = half * 128 + warp * 16 + g;
            int col = nt * 8 + 2 * tg;
            *(float2*)&sY[row * 66 + col]       = make_float2(c[nt][0], c[nt][1]);
            *(float2*)&sY[(row + 8) * 66 + col] = make_float2(c[nt][2], c[nt][3]);
        }
    }

    // ---- GEMM2: Xf = A2 @ Y (R4-s2 body, Y read from smem) ----
    float c2[4][4];
#pragma unroll
    for (int i = 0; i < 4; i++)
#pragma unroll
        for (int j = 0; j < 4; j++) c2[i][j] = 0.f;

    for (int kc = 0; kc < 16; kc++) {
        __syncthreads();
        for (int i = tid; i < 128 * 32; i += 256) {
            int row = i >> 5, col = i & 31;
            sA[row * 33 + col] = g_A2[row * 512 + kc * 32 + col];
        }
        __syncthreads();
#pragma unroll
        for (int ks = 0; ks < 4; ks++) {
            unsigned ah[4], al[4];
            split2(sA[(warp * 16 + g    ) * 33 + ks * 8 + tg    ], ah[0], al[0]);
            split2(sA[(warp * 16 + g + 8) * 33 + ks * 8 + tg    ], ah[1], al[1]);
            split2(sA[(warp * 16 + g    ) * 33 + ks * 8 + tg + 4], ah[2], al[2]);
            split2(sA[(warp * 16 + g + 8) * 33 + ks * 8 + tg + 4], ah[3], al[3]);
            int k0 = ks * 8 + tg, k1 = k0 + 4;
#pragma unroll
            for (int nt = 0; nt < 4; nt++) {
                unsigned bh[2], bl[2];
                int n = nt * 8 + g;
                split2(sY[(kc * 16 + (k0 >> 1)) * 66 + 2 * n + (k0 & 1)], bh[0], bl[0]);
                split2(sY[(kc * 16 + (k1 >> 1)) * 66 + 2 * n + (k1 & 1)], bh[1], bl[1]);
                mma3(c2[nt], ah, al, bh, bl);
            }
        }
    }
    float* xf = (float*)g_Xf + (size_t)bi * 4096;
#pragma unroll
    for (int nt = 0; nt < 4; nt++) {
        int m0 = warp * 16 + g, m1 = m0 + 8;
        int n0 = nt * 8 + 2 * tg, n1 = n0 + 1;
        xf[(m0 >> 1) * 64 + 2 * n0 + (m0 & 1)] = c2[nt][0];
        xf[(m0 >> 1) * 64 + 2 * n1 + (m0 & 1)] = c2[nt][1];
        xf[(m1 >> 1) * 64 + 2 * n0 + (m1 & 1)] = c2[nt][2];
        xf[(m1 >> 1) * 64 + 2 * n1 + (m1 & 1)] = c2[nt][3];
    }
}

// ---------------- K3a (FFMA, unchanged R4): t = sum_i Xf * w{1|2} ----------------
__global__ void __launch_bounds__(256) k3a_mixx(const float* __restrict__ wx1,
                                                const float* __restrict__ wx2) {
    __shared__ float2 sX[CINN][M2N];
    __shared__ float2 sW[CINN][COUTT];
    const int tid = threadIdx.x;
    const int kxi = blockIdx.x, b = blockIdx.y;
    const int m = (kxi < 32) ? kxi : (kxi - 32);
    const float2* wsrc = (const float2*)((kxi < 32) ? wx1 : wx2);

    for (int idx = tid; idx < CINN * M2N; idx += 256) {
        int i = idx >> 5, k = idx & 31;
        sX[i][k] = g_Xf[((b * CINN + i) * KXN + kxi) * M2N + k];
    }
    for (int idx = tid; idx < CINN * COUTT; idx += 256) {
        int i = idx >> 6, c = idx & 63;
        sW[i][c] = wsrc[(i * COUTT + c) * M1N + m];
    }
    __syncthreads();

    const int ky = tid & 31;
    const int cb = (tid >> 5) << 3;
    float2 acc[8];
#pragma unroll
    for (int j = 0; j < 8; j++) acc[j] = make_float2(0.f, 0.f);
    for (int i = 0; i < CINN; i++) {
        float2 xv = sX[i][ky];
#pragma unroll
        for (int j = 0; j < 8; j++) {
            float2 wv = sW[i][cb + j];
            acc[j].x = fmaf(xv.x, wv.x, fmaf(-xv.y, wv.y, acc[j].x));
            acc[j].y = fmaf(xv.x, wv.y, fmaf( xv.y, wv.x, acc[j].y));
        }
    }
#pragma unroll
    for (int j = 0; j < 8; j++)
        g_T[((b * COUTT + cb + j) * KXN + kxi) * M2N + ky] = acc[j];
}

// ---------------- K3b (FFMA, unchanged R4): OutF = sum_c t * wy ----------------
__global__ void __launch_bounds__(256) k3b_mixy(const float* __restrict__ wy) {
    __shared__ float2 sT[32][KXN];
    __shared__ float2 sWy[32][COUTT];
    const int tid = threadIdx.x;
    const int ky = blockIdx.x, b = blockIdx.y;
    const int kxi = tid & 63;
    const int ob = (tid >> 6) << 4;
    const float2* wyp = (const float2*)wy;

    float2 acc[16];
#pragma unroll
    for (int j = 0; j < 16; j++) acc[j] = make_float2(0.f, 0.f);

    for (int cb = 0; cb < COUTT; cb += 32) {
        __syncthreads();
        for (int idx = tid; idx < 32 * KXN; idx += 256) {
            int cl = idx >> 6, kk = idx & 63;
            sT[cl][kk] = g_T[((b * COUTT + cb + cl) * KXN + kk) * M2N + ky];
        }
        for (int idx = tid; idx < 32 * COUTT; idx += 256) {
            int cl = idx >> 6, o = idx & 63;
            sWy[cl][o] = wyp[((cb + cl) * COUTT + o) * M2N + ky];
        }
        __syncthreads();
        for (int cl = 0; cl < 32; cl++) {
            float2 tv = sT[cl][kxi];
#pragma unroll
            for (int j = 0; j < 16; j++) {
                float2 wv = sWy[cl][ob + j];
                acc[j].x = fmaf(tv.x, wv.x, fmaf(-tv.y, wv.y, acc[j].x));
                acc[j].y = fmaf(tv.x, wv.y, fmaf( tv.y, wv.x, acc[j].y));
            }
        }
    }
#pragma unroll
    for (int j = 0; j < 16; j++)
        g_OutF[((b * COUTT + ob + j) * KXN + kxi) * M2N + ky] = acc[j];
}

// ---------------- S56 fused: per (b,o): Z = A5 @ OutF in smem, then out = Z @ C6 ----------------
// dyn smem: sZ[256][66] | sA5[256][17] (reused as sC[32][129]) | sF[64][66]
#define S56_SZ  (256 * 66)
#define S56_SA  (256 * 17)
#define S56_SF  (64 * 66)
#define S56_SMEM ((S56_SZ + S56_SA + S56_SF) * 4)

__global__ void __launch_bounds__(256) s56_fused(float* __restrict__ out) {
    extern __shared__ float sm[];
    float* sZ  = sm;                 // [256][66]
    float* sA5 = sm + S56_SZ;        // [256][17] phase1 / [32][129] phase2 (sC)
    float* sF  = sA5 + S56_SA;       // [64][66]
    const int tid = threadIdx.x, warp = tid >> 5, lane = tid & 31;
    const int g = lane >> 2, tg = lane & 3;
    const int bo = blockIdx.x;

    const float* outf = (const float*)g_OutF + (size_t)bo * 4096;
    for (int i = tid; i < 64 * 64; i += 256)
        sF[(i >> 6) * 66 + (i & 63)] = outf[i];

    // ---- phase 1: Z = A5 @ OutF (R4-s5 body), both M-halves ----
    for (int mh = 0; mh < 2; mh++) {
        float c[2][4][4];
#pragma unroll
        for (int a = 0; a < 2; a++)
#pragma unroll
            for (int i = 0; i < 4; i++)
#pragma unroll
                for (int j = 0; j < 4; j++) c[a][i][j] = 0.f;

        for (int kc = 0; kc < 8; kc++) {
            __syncthreads();
            for (int i = tid; i < 256 * 16; i += 256) {
                int row = i >> 4, col = i & 15;
                sA5[row * 17 + col] = g_A5[(mh * 256 + row) * 128 + kc * 16 + col];
            }
            __syncthreads();
#pragma unroll
            for (int ks = 0; ks < 2; ks++) {
                int kg0 = kc * 16 + ks * 8 + tg, kg1 = kg0 + 4;
                unsigned bharr[4][2], blarr[4][2];
#pragma unroll
                for (int nt = 0; nt < 4; nt++) {
                    int n = nt * 8 + g;
                    split2(sF[(kg0 >> 1) * 66 + 2 * n + (kg0 & 1)], bharr[nt][0], blarr[nt][0]);
                    split2(sF[(kg1 >> 1) * 66 + 2 * n + (kg1 & 1)], bharr[nt][1], blarr[nt][1]);
                }
#pragma unroll
                for (int mt = 0; mt < 2; mt++) {
                    int r = warp * 32 + mt * 16;
                    unsigned ah[4], al[4];
                    split2(sA5[(r + g    ) * 17 + ks * 8 + tg    ], ah[0], al[0]);
                    split2(sA5[(r + g + 8) * 17 + ks * 8 + tg    ], ah[1], al[1]);
                    split2(sA5[(r + g    ) * 17 + ks * 8 + tg + 4], ah[2], al[2]);
                    split2(sA5[(r + g + 8) * 17 + ks * 8 + tg + 4], ah[3], al[3]);
#pragma unroll
                    for (int nt = 0; nt < 4; nt++)
                        mma3(c[mt][nt], ah, al, bharr[nt], blarr[nt]);
                }
            }
        }
#pragma unroll
        for (int mt = 0; mt < 2; mt++)
#pragma unroll
            for (int nt = 0; nt < 4; nt++) {
                int m0 = mh * 256 + warp * 32 + mt * 16 + g, m1 = m0 + 8;
                int n0 = nt * 8 + 2 * tg, n1 = n0 + 1;
                sZ[(m0 >> 1) * 66 + 2 * n0 + (m0 & 1)] = c[mt][nt][0];
                sZ[(m0 >> 1) * 66 + 2 * n1 + (m0 & 1)] = c[mt][nt][1];
                sZ[(m1 >> 1) * 66 + 2 * n0 + (m1 & 1)] = c[mt][nt][2];
                sZ[(m1 >> 1) * 66 + 2 * n1 + (m1 & 1)] = c[mt][nt][3];
            }
    }
    __syncthreads();

    // ---- phase 2: out = Z @ C6 (R4-s6 body), 4 quadrants ----
    float* sC = sA5;                  // [32][129]
    float* orow = out + (size_t)bo * 65536;
#pragma unroll 1
    for (int mt2 = 0; mt2 < 2; mt2++)
#pragma unroll 1
    for (int nt2 = 0; nt2 < 2; nt2++) {
        float c[16][4];
#pragma unroll
        for (int i = 0; i < 16; i++)
#pragma unroll
            for (int j = 0; j < 4; j++) c[i][j] = 0.f;

        for (int kc = 0; kc < 2; kc++) {
            __syncthreads();
            for (int i = tid; i < 32 * 128; i += 256) {
                int k = i >> 7, n = i & 127;
                sC[k * 129 + n] = g_C6[(kc * 32 + k) * 256 + nt2 * 128 + n];
            }
            __syncthreads();
#pragma unroll
            for (int ks = 0; ks < 4; ks++) {
                unsigned ah[4], al[4];
                int rb = mt2 * 128 + warp * 16;
                int kk = kc * 32 + ks * 8 + tg;
                split2(sZ[(rb + g    ) * 66 + kk    ], ah[0], al[0]);
                split2(sZ[(rb + g + 8) * 66 + kk    ], ah[1], al[1]);
                split2(sZ[(rb + g    ) * 66 + kk + 4], ah[2], al[2]);
                split2(sZ[(rb + g + 8) * 66 + kk + 4], ah[3], al[3]);
#pragma unroll
                for (int nt = 0; nt < 16; nt++) {
                    unsigned bh[2], bl[2];
                    split2(sC[(ks * 8 + tg    ) * 129 + nt * 8 + g], bh[0], bl[0]);
                    split2(sC[(ks * 8 + tg + 4) * 129 + nt * 8 + g], bh[1], bl[1]);
                    mma3(c[nt], ah, al, bh, bl);
                }
            }
        }
#pragma unroll
        for (int nt = 0; nt < 16; nt++) {
            int h = mt2 * 128 + warp * 16 + g;
            int w = nt2 * 128 + nt * 8 + 2 * tg;
            *(float2*)&orow[(h)     * 256 + w] = make_float2(c[nt][0], c[nt][1]);
            *(float2*)&orow[(h + 8) * 256 + w] = make_float2(c[nt][2], c[nt][3]);
        }
    }
}

extern "C" void kernel_launch(void* const* d_in, const int* in_sizes, int n_in,
                              void* d_out, int out_size) {
    const float* x   = (const float*)d_in[0];
    const float* wx1 = (const float*)d_in[1];
    const float* wx2 = (const float*)d_in[2];
    const float* wy  = (const float*)d_in[3];
    float* out = (float*)d_out;

    cudaFuncSetAttribute(s12_fused, cudaFuncAttributeMaxDynamicSharedMemorySize, S12_SMEM);
    cudaFuncSetAttribute(s56_fused, cudaFuncAttributeMaxDynamicSharedMemorySize, S56_SMEM);

    fill_all<<<256, 256>>>();
    s12_fused<<<1024, 256, S12_SMEM>>>(x);              // W-DFT + H-DFT fused
    k3a_mixx<<<dim3(KXN, BB), 256>>>(wx1, wx2);
    k3b_mixy<<<dim3(M2N, BB), 256>>>(wy);
    s56_fused<<<1024, 256, S56_SMEM>>>(out);            // inv-H + irfft-W fused
}

// round 10
// speedup vs baseline: 1.6061x; 1.0139x over previous
#include <cuda_runtime.h>
#include <math.h>

#define BB    16
#define CINN  64
#define COUTT 64
#define M1N   32
#define M2N   32
#define KXN   64

// ---------------- scratch ----------------
__device__ float  g_Y1[BB * CINN * 256 * 64];          // [b,i,h][2ky+t]  67MB
__device__ float2 g_Xf  [BB * CINN  * KXN * M2N];
__device__ float2 g_T   [BB * COUTT * KXN * M2N];
__device__ float2 g_OutF[BB * COUTT * KXN * M2N];
__device__ float  g_Zre[BB * COUTT * 256 * 32];        // [b,o][h][ky] 33.5MB
__device__ float  g_Zim[BB * COUTT * 256 * 32];
// stationary matrices (plain fp32, split per use — locked R4 format)
__device__ float g_B1c[144 * 32];   // folded fwd W-DFT cos (re), scale 1/16
__device__ float g_B1s[128 * 32];   // folded fwd W-DFT sin (im), scale 1/16
__device__ float g_A2[128 * 512];   // fwd H-DFT, scale 1/16
__device__ float g_A5[512 * 128];   // inv H-DFT
__device__ float g_C6c[32 * 136];   // folded irfft cos
__device__ float g_C6s[32 * 136];   // folded irfft sin

// ---------------- tf32 mma helpers ----------------
__device__ __forceinline__ unsigned tf32of(float x) {
    unsigned r; asm("cvt.rna.tf32.f32 %0,%1;" : "=r"(r) : "f"(x)); return r;
}
__device__ __forceinline__ void split2(float x, unsigned& h, unsigned& l) {
    h = tf32of(x);
    l = tf32of(x - __uint_as_float(h));
}
__device__ __forceinline__ void mma1(float* c, const unsigned* a, const unsigned* b) {
    asm volatile(
        "mma.sync.aligned.m16n8k8.row.col.f32.tf32.tf32.f32 "
        "{%0,%1,%2,%3},{%4,%5,%6,%7},{%8,%9},{%0,%1,%2,%3};"
        : "+f"(c[0]), "+f"(c[1]), "+f"(c[2]), "+f"(c[3])
        : "r"(a[0]), "r"(a[1]), "r"(a[2]), "r"(a[3]), "r"(b[0]), "r"(b[1]));
}
__device__ __forceinline__ void mma3(float* c, const unsigned* ah, const unsigned* al,
                                     const unsigned* bh, const unsigned* bl) {
    mma1(c, ah, bh);
    mma1(c, al, bh);
    mma1(c, ah, bl);
}

// ---------------- single fill kernel ----------------
__global__ void __launch_bounds__(256) fill_all() {
    int idx = blockIdx.x * 256 + threadIdx.x;           // 65536 threads
    // A2 [128][512]
    {
        int row = idx >> 9, col = idx & 511;
        int kxi = row >> 1, t = row & 1, h = col >> 1, s2 = col & 1;
        int kx = (kxi < 32) ? kxi : (192 + kxi);
        float s, c; sincospif((float)((kx * h) & 255) / 128.0f, &s, &c);
        g_A2[idx] = ((t == 0) ? ((s2 == 0) ? c : s) : ((s2 == 0) ? -s : c)) * (1.0f / 16.0f);
    }
    // A5 [512][128]
    {
        int row = idx >> 7, col = idx & 127;
        int h = row >> 1, t = row & 1, kxi = col >> 1, s2 = col & 1;
        int kx = (kxi < 32) ? kxi : (192 + kxi);
        float s, c; sincospif((float)((kx * h) & 255) / 128.0f, &s, &c);
        g_A5[idx] = (t == 0) ? ((s2 == 0) ? c : -s) : ((s2 == 0) ? s : c);
    }
    // B1c [144][32]
    if (idx < 144 * 32) {
        int kk = idx >> 5, ky = idx & 31;
        float v;
        if (kk == 0)        v = 1.0f;
        else if (kk == 1)   v = (ky & 1) ? -1.0f : 1.0f;
        else if (kk <= 128) v = cospif((float)(((kk - 1) * ky) & 255) / 128.0f);
        else                v = 0.0f;
        g_B1c[idx] = v * (1.0f / 16.0f);
    }
    // B1s [128][32]
    if (idx < 128 * 32) {
        int kk = idx >> 5, ky = idx & 31;
        g_B1s[idx] = -sinpif((float)(((kk + 1) * ky) & 255) / 128.0f) * (1.0f / 16.0f);
    }
    // C6c / C6s [32][136]
    if (idx < 32 * 136) {
        int ky = idx / 136, w = idx % 136;
        float base = ((ky == 0) ? 1.0f : 2.0f) * (1.0f / 256.0f);
        g_C6c[idx] = (w <= 128) ? base * cospif((float)((ky * w) & 255) / 128.0f) : 0.0f;
        g_C6s[idx] = (w >= 1 && w <= 128 && ky >= 1)
                   ? (2.0f / 256.0f) * sinpif((float)((ky * w) & 255) / 128.0f) : 0.0f;
    }
}

// ---------------- S1 folded: per 128 rows: Yre (K=144) + Yim (K=128) GEMMs ----------------
__global__ void __launch_bounds__(256) s1_wdft(const float* __restrict__ x) {
    __shared__ float sE[128][17];      // 8.7KB folded data chunk
    __shared__ float sB[16][33];       // 2.1KB B chunk
    const int tid = threadIdx.x, warp = tid >> 5, lane = tid & 31;
    const int g = lane >> 2, tg = lane & 3;
    const int r0 = blockIdx.x * 128;
    const float* xs = x + (size_t)r0 * 256;

    // ---- GEMM-re: Yre = [x0, x128, E(1..127)] @ B1c ----
    {
        float c[4][4];
#pragma unroll
        for (int i = 0; i < 4; i++)
#pragma unroll
            for (int j = 0; j < 4; j++) c[i][j] = 0.f;

        for (int kc = 0; kc < 9; kc++) {
            __syncthreads();
            for (int i = tid; i < 128 * 16; i += 256) {
                int row = i >> 4, j = i & 15;
                int kk = kc * 16 + j;
                float v;
                if (kk == 0)        v = xs[(size_t)row * 256];
                else if (kk == 1)   v = xs[(size_t)row * 256 + 128];
                else if (kk <= 128) {
                    int w = kk - 1;
                    v = xs[(size_t)row * 256 + w] + xs[(size_t)row * 256 + 256 - w];
                } else v = 0.f;
                sE[row][j] = v;
            }
            for (int i = tid; i < 16 * 32; i += 256) {
                int k = i >> 5, n = i & 31;
                sB[k][n] = g_B1c[(kc * 16 + k) * 32 + n];
            }
            __syncthreads();
#pragma unroll
            for (int ks = 0; ks < 2; ks++) {
                unsigned ah[4], al[4];
                split2(sE[warp * 16 + g    ][ks * 8 + tg    ], ah[0], al[0]);
                split2(sE[warp * 16 + g + 8][ks * 8 + tg    ], ah[1], al[1]);
                split2(sE[warp * 16 + g    ][ks * 8 + tg + 4], ah[2], al[2]);
                split2(sE[warp * 16 + g + 8][ks * 8 + tg + 4], ah[3], al[3]);
#pragma unroll
                for (int nt = 0; nt < 4; nt++) {
                    unsigned bh[2], bl[2];
                    split2(sB[ks * 8 + tg    ][nt * 8 + g], bh[0], bl[0]);
                    split2(sB[ks * 8 + tg + 4][nt * 8 + g], bh[1], bl[1]);
                    mma3(c[nt], ah, al, bh, bl);
                }
            }
        }
#pragma unroll
        for (int nt = 0; nt < 4; nt++) {
            int row = r0 + warp * 16 + g;
            int ky0 = nt * 8 + 2 * tg;
            g_Y1[(size_t)row * 64 + 2 * ky0]           = c[nt][0];
            g_Y1[(size_t)row * 64 + 2 * (ky0 + 1)]     = c[nt][1];
            g_Y1[(size_t)(row + 8) * 64 + 2 * ky0]     = c[nt][2];
            g_Y1[(size_t)(row + 8) * 64 + 2 * (ky0 + 1)] = c[nt][3];
        }
    }

    // ---- GEMM-im: Yim = O(1..128) @ B1s ----
    {
        float c[4][4];
#pragma unroll
        for (int i = 0; i < 4; i++)
#pragma unroll
            for (int j = 0; j < 4; j++) c[i][j] = 0.f;

        for (int kc = 0; kc < 8; kc++) {
            __syncthreads();
            for (int i = tid; i < 128 * 16; i += 256) {
                int row = i >> 4, j = i & 15;
                int w = kc * 16 + j + 1;    // 1..128
                sE[row][j] = xs[(size_t)row * 256 + w] - xs[(size_t)row * 256 + ((256 - w) & 255)]
                             * ((w == 128) ? 1.0f : 1.0f);
            }
            for (int i = tid; i < 16 * 32; i += 256) {
                int k = i >> 5, n = i & 31;
                sB[k][n] = g_B1s[(kc * 16 + k) * 32 + n];
            }
            __syncthreads();
#pragma unroll
            for (int ks = 0; ks < 2; ks++) {
                unsigned ah[4], al[4];
                split2(sE[warp * 16 + g    ][ks * 8 + tg    ], ah[0], al[0]);
                split2(sE[warp * 16 + g + 8][ks * 8 + tg    ], ah[1], al[1]);
                split2(sE[warp * 16 + g    ][ks * 8 + tg + 4], ah[2], al[2]);
                split2(sE[warp * 16 + g + 8][ks * 8 + tg + 4], ah[3], al[3]);
#pragma unroll
                for (int nt = 0; nt < 4; nt++) {
                    unsigned bh[2], bl[2];
                    split2(sB[ks * 8 + tg    ][nt * 8 + g], bh[0], bl[0]);
                    split2(sB[ks * 8 + tg + 4][nt * 8 + g], bh[1], bl[1]);
                    mma3(c[nt], ah, al, bh, bl);
                }
            }
        }
#pragma unroll
        for (int nt = 0; nt < 4; nt++) {
            int row = r0 + warp * 16 + g;
            int ky0 = nt * 8 + 2 * tg;
            g_Y1[(size_t)row * 64 + 2 * ky0 + 1]           = c[nt][0];
            g_Y1[(size_t)row * 64 + 2 * (ky0 + 1) + 1]     = c[nt][1];
            g_Y1[(size_t)(row + 8) * 64 + 2 * ky0 + 1]     = c[nt][2];
            g_Y1[(size_t)(row + 8) * 64 + 2 * (ky0 + 1) + 1] = c[nt][3];
        }
    }
}

// ---------------- S2 (exact R4): Xf = A2 @ Y1slab ----------------
__global__ void __launch_bounds__(256) s2_hdft() {
    __shared__ float sA[128][33];
    __shared__ float sY[16][66];
    const int tid = threadIdx.x, warp = tid >> 5, lane = tid & 31;
    const int g = lane >> 2, tg = lane & 3;
    const int bi = blockIdx.x;

    float c[4][4];
#pragma unroll
    for (int i = 0; i < 4; i++)
#pragma unroll
        for (int j = 0; j < 4; j++) c[i][j] = 0.f;

    for (int kc = 0; kc < 16; kc++) {
        __syncthreads();
        for (int i = tid; i < 128 * 32; i += 256) {
            int row = i >> 5, col = i & 31;
            sA[row][col] = g_A2[row * 512 + kc * 32 + col];
        }
        for (int i = tid; i < 16 * 64; i += 256) {
            int h = i >> 6, cc = i & 63;
            sY[h][cc] = g_Y1[((size_t)bi * 256 + kc * 16 + h) * 64 + cc];
        }
        __syncthreads();
#pragma unroll
        for (int ks = 0; ks < 4; ks++) {
            unsigned ah[4], al[4];
            split2(sA[warp * 16 + g    ][ks * 8 + tg    ], ah[0], al[0]);
            split2(sA[warp * 16 + g + 8][ks * 8 + tg    ], ah[1], al[1]);
            split2(sA[warp * 16 + g    ][ks * 8 + tg + 4], ah[2], al[2]);
            split2(sA[warp * 16 + g + 8][ks * 8 + tg + 4], ah[3], al[3]);
            int k0 = ks * 8 + tg, k1 = k0 + 4;
#pragma unroll
            for (int nt = 0; nt < 4; nt++) {
                unsigned bh[2], bl[2];
                int n = nt * 8 + g;
                split2(sY[k0 >> 1][2 * n + (k0 & 1)], bh[0], bl[0]);
                split2(sY[k1 >> 1][2 * n + (k1 & 1)], bh[1], bl[1]);
                mma3(c[nt], ah, al, bh, bl);
            }
        }
    }
    float* xf = (float*)g_Xf + (size_t)bi * 4096;
#pragma unroll
    for (int nt = 0; nt < 4; nt++) {
        int m0 = warp * 16 + g, m1 = m0 + 8;
        int n0 = nt * 8 + 2 * tg, n1 = n0 + 1;
        xf[(m0 >> 1) * 64 + 2 * n0 + (m0 & 1)] = c[nt][0];
        xf[(m0 >> 1) * 64 + 2 * n1 + (m0 & 1)] = c[nt][1];
        xf[(m1 >> 1) * 64 + 2 * n0 + (m1 & 1)] = c[nt][2];
        xf[(m1 >> 1) * 64 + 2 * n1 + (m1 & 1)] = c[nt][3];
    }
}

// ---------------- K3a (exact R4) ----------------
__global__ void __launch_bounds__(256) k3a_mixx(const float* __restrict__ wx1,
                                                const float* __restrict__ wx2) {
    __shared__ float2 sX[CINN][M2N];
    __shared__ float2 sW[CINN][COUTT];
    const int tid = threadIdx.x;
    const int kxi = blockIdx.x, b = blockIdx.y;
    const int m = (kxi < 32) ? kxi : (kxi - 32);
    const float2* wsrc = (const float2*)((kxi < 32) ? wx1 : wx2);

    for (int idx = tid; idx < CINN * M2N; idx += 256) {
        int i = idx >> 5, k = idx & 31;
        sX[i][k] = g_Xf[((b * CINN + i) * KXN + kxi) * M2N + k];
    }
    for (int idx = tid; idx < CINN * COUTT; idx += 256) {
        int i = idx >> 6, c = idx & 63;
        sW[i][c] = wsrc[(i * COUTT + c) * M1N + m];
    }
    __syncthreads();

    const int ky = tid & 31;
    const int cb = (tid >> 5) << 3;
    float2 acc[8];
#pragma unroll
    for (int j = 0; j < 8; j++) acc[j] = make_float2(0.f, 0.f);
    for (int i = 0; i < CINN; i++) {
        float2 xv = sX[i][ky];
#pragma unroll
        for (int j = 0; j < 8; j++) {
            float2 wv = sW[i][cb + j];
            acc[j].x = fmaf(xv.x, wv.x, fmaf(-xv.y, wv.y, acc[j].x));
            acc[j].y = fmaf(xv.x, wv.y, fmaf( xv.y, wv.x, acc[j].y));
        }
    }
#pragma unroll
    for (int j = 0; j < 8; j++)
        g_T[((b * COUTT + cb + j) * KXN + kxi) * M2N + ky] = acc[j];
}

// ---------------- K3b (exact R4) ----------------
__global__ void __launch_bounds__(256) k3b_mixy(const float* __restrict__ wy) {
    __shared__ float2 sT[32][KXN];
    __shared__ float2 sWy[32][COUTT];
    const int tid = threadIdx.x;
    const int ky = blockIdx.x, b = blockIdx.y;
    const int kxi = tid & 63;
    const int ob = (tid >> 6) << 4;
    const float2* wyp = (const float2*)wy;

    float2 acc[16];
#pragma unroll
    for (int j = 0; j < 16; j++) acc[j] = make_float2(0.f, 0.f);

    for (int cb = 0; cb < COUTT; cb += 32) {
        __syncthreads();
        for (int idx = tid; idx < 32 * KXN; idx += 256) {
            int cl = idx >> 6, kk = idx & 63;
            sT[cl][kk] = g_T[((b * COUTT + cb + cl) * KXN + kk) * M2N + ky];
        }
        for (int idx = tid; idx < 32 * COUTT; idx += 256) {
            int cl = idx >> 6, o = idx & 63;
            sWy[cl][o] = wyp[((cb + cl) * COUTT + o) * M2N + ky];
        }
        __syncthreads();
        for (int cl = 0; cl < 32; cl++) {
            float2 tv = sT[cl][kxi];
#pragma unroll
            for (int j = 0; j < 16; j++) {
                float2 wv = sWy[cl][ob + j];
                acc[j].x = fmaf(tv.x, wv.x, fmaf(-tv.y, wv.y, acc[j].x));
                acc[j].y = fmaf(tv.x, wv.y, fmaf( tv.y, wv.x, acc[j].y));
            }
        }
    }
#pragma unroll
    for (int j = 0; j < 16; j++)
        g_OutF[((b * COUTT + ob + j) * KXN + kxi) * M2N + ky] = acc[j];
}

// ---------------- S5 (R4 mainloop, plane epilogue): Z = A5 @ OutFslab ----------------
__global__ void __launch_bounds__(256) s5_invh() {
    __shared__ float sA[256][17];
    __shared__ float sF[64][66];
    const int tid = threadIdx.x, warp = tid >> 5, lane = tid & 31;
    const int g = lane >> 2, tg = lane & 3;
    const int mh = blockIdx.x, bo = blockIdx.y;

    const float* outf = (const float*)g_OutF + (size_t)bo * 4096;
    for (int i = tid; i < 64 * 64; i += 256) {
        int r = i >> 6, cc = i & 63;
        sF[r][cc] = outf[r * 64 + cc];
    }

    float c[2][4][4];
#pragma unroll
    for (int a = 0; a < 2; a++)
#pragma unroll
        for (int i = 0; i < 4; i++)
#pragma unroll
            for (int j = 0; j < 4; j++) c[a][i][j] = 0.f;

    for (int kc = 0; kc < 8; kc++) {
        __syncthreads();
        for (int i = tid; i < 256 * 16; i += 256) {
            int row = i >> 4, col = i & 15;
            sA[row][col] = g_A5[(mh * 256 + row) * 128 + kc * 16 + col];
        }
        __syncthreads();
#pragma unroll
        for (int ks = 0; ks < 2; ks++) {
            int kg0 = kc * 16 + ks * 8 + tg, kg1 = kg0 + 4;
            unsigned bharr[4][2], blarr[4][2];
#pragma unroll
            for (int nt = 0; nt < 4; nt++) {
                int n = nt * 8 + g;
                split2(sF[kg0 >> 1][2 * n + (kg0 & 1)], bharr[nt][0], blarr[nt][0]);
                split2(sF[kg1 >> 1][2 * n + (kg1 & 1)], bharr[nt][1], blarr[nt][1]);
            }
#pragma unroll
            for (int mt = 0; mt < 2; mt++) {
                int r = warp * 32 + mt * 16;
                unsigned ah[4], al[4];
                split2(sA[r + g    ][ks * 8 + tg    ], ah[0], al[0]);
                split2(sA[r + g + 8][ks * 8 + tg    ], ah[1], al[1]);
                split2(sA[r + g    ][ks * 8 + tg + 4], ah[2], al[2]);
                split2(sA[r + g + 8][ks * 8 + tg + 4], ah[3], al[3]);
#pragma unroll
                for (int nt = 0; nt < 4; nt++)
                    mma3(c[mt][nt], ah, al, bharr[nt], blarr[nt]);
            }
        }
    }
    float* zre = g_Zre + (size_t)bo * 8192;
    float* zim = g_Zim + (size_t)bo * 8192;
#pragma unroll
    for (int mt = 0; mt < 2; mt++)
#pragma unroll
        for (int nt = 0; nt < 4; nt++) {
            int m0 = mh * 256 + warp * 32 + mt * 16 + g, m1 = m0 + 8;
            int n0 = nt * 8 + 2 * tg, n1 = n0 + 1;
            float* p0 = (m0 & 1) ? zim : zre;
            float* p1 = (m1 & 1) ? zim : zre;
            p0[(m0 >> 1) * 32 + n0] = c[mt][nt][0];
            p0[(m0 >> 1) * 32 + n1] = c[mt][nt][1];
            p1[(m1 >> 1) * 32 + n0] = c[mt][nt][2];
            p1[(m1 >> 1) * 32 + n1] = c[mt][nt][3];
        }
}

// ---------------- S6 folded: A = Zre@C6c, B = Zim@C6s; out[w]=A−B, out[256−w]=A+B ----------------
// dyn smem: sZre[128][33] | sZim[128][33] | sCc[32][137] | sCs[32][137]
#define S6_SMEM ((128*33*2 + 32*137*2) * 4)

__global__ void __launch_bounds__(256) s6_invw(float* __restrict__ out) {
    extern __shared__ float sm6[];
    float* sZre = sm6;                       // [128][33]
    float* sZim = sZre + 128 * 33;           // [128][33]
    float* sCc  = sZim + 128 * 33;           // [32][137]
    float* sCs  = sCc + 32 * 137;            // [32][137]
    const int tid = threadIdx.x, warp = tid >> 5, lane = tid & 31;
    const int g = lane >> 2, tg = lane & 3;
    const int mt2 = blockIdx.x, bo = blockIdx.y;

    const float* zre = g_Zre + (size_t)bo * 8192 + mt2 * 128 * 32;
    const float* zim = g_Zim + (size_t)bo * 8192 + mt2 * 128 * 32;
    for (int i = tid; i < 128 * 32; i += 256) {
        int r = i >> 5, cc = i & 31;
        sZre[r * 33 + cc] = zre[i];
        sZim[r * 33 + cc] = zim[i];
    }
    for (int i = tid; i < 32 * 136; i += 256) {
        int k = i / 136, n = i % 136;
        sCc[k * 137 + n] = g_C6c[i];
        sCs[k * 137 + n] = g_C6s[i];
    }
    __syncthreads();

    // preload A-operand fragments (K=32: 4 ksteps), re and im
    unsigned aReh[4][4], aRel[4][4], aImh[4][4], aIml[4][4];
    {
        int r0 = warp * 16 + g, r1 = r0 + 8;
#pragma unroll
        for (int ks = 0; ks < 4; ks++) {
            int k0 = ks * 8 + tg, k1 = k0 + 4;
            split2(sZre[r0 * 33 + k0], aReh[ks][0], aRel[ks][0]);
            split2(sZre[r1 * 33 + k0], aReh[ks][1], aRel[ks][1]);
            split2(sZre[r0 * 33 + k1], aReh[ks][2], aRel[ks][2]);
            split2(sZre[r1 * 33 + k1], aReh[ks][3], aRel[ks][3]);
            split2(sZim[r0 * 33 + k0], aImh[ks][0], aIml[ks][0]);
            split2(sZim[r1 * 33 + k0], aImh[ks][1], aIml[ks][1]);
            split2(sZim[r0 * 33 + k1], aImh[ks][2], aIml[ks][2]);
            split2(sZim[r1 * 33 + k1], aImh[ks][3], aIml[ks][3]);
        }
    }

    float* orow = out + (size_t)bo * 65536 + (size_t)mt2 * 128 * 256;
    const int m = warp * 16 + g;

#pragma unroll 1
    for (int nt = 0; nt < 17; nt++) {
        float accA[4] = {0.f, 0.f, 0.f, 0.f};
        float accB[4] = {0.f, 0.f, 0.f, 0.f};
#pragma unroll
        for (int ks = 0; ks < 4; ks++) {
            unsigned bh[2], bl[2];
            split2(sCc[(ks * 8 + tg) * 137 + nt * 8 + g], bh[0], bl[0]);
            split2(sCc[(ks * 8 + tg + 4) * 137 + nt * 8 + g], bh[1], bl[1]);
            mma3(accA, aReh[ks], aRel[ks], bh, bl);
            split2(sCs[(ks * 8 + tg) * 137 + nt * 8 + g], bh[0], bl[0]);
            split2(sCs[(ks * 8 + tg + 4) * 137 + nt * 8 + g], bh[1], bl[1]);
            mma3(accB, aImh[ks], aIml[ks], bh, bl);
        }
        int w0 = nt * 8 + 2 * tg;
#pragma unroll
        for (int p = 0; p < 2; p++) {
            int w = w0 + p;
            if (w > 128) continue;           // only trims nt==16 tail
            float v0 = accA[p]     - accB[p];
            float v1 = accA[p + 2] - accB[p + 2];
            orow[m * 256 + w]       = v0;
            orow[(m + 8) * 256 + w] = v1;
            if (w >= 1 && w <= 127) {
                orow[m * 256 + 256 - w]       = accA[p]     + accB[p];
                orow[(m + 8) * 256 + 256 - w] = accA[p + 2] + accB[p + 2];
            }
        }
    }
}

extern "C" void kernel_launch(void* const* d_in, const int* in_sizes, int n_in,
                              void* d_out, int out_size) {
    const float* x   = (const float*)d_in[0];
    const float* wx1 = (const float*)d_in[1];
    const float* wx2 = (const float*)d_in[2];
    const float* wy  = (const float*)d_in[3];
    float* out = (float*)d_out;

    cudaFuncSetAttribute(s6_invw, cudaFuncAttributeMaxDynamicSharedMemorySize, S6_SMEM);

    fill_all<<<256, 256>>>();
    s1_wdft<<<2048, 256>>>(x);                 // folded W-DFT (re + im GEMMs)
    s2_hdft<<<1024, 256>>>();                  // H-DFT
    k3a_mixx<<<dim3(KXN, BB), 256>>>(wx1, wx2);
    k3b_mixy<<<dim3(M2N, BB), 256>>>(wy);
    s5_invh<<<dim3(2, 1024), 256>>>();         // inverse H (plane epilogue)
    s6_invw<<<dim3(2, 1024), 256, S6_SMEM>>>(out);  // folded irfft-W
}

// round 11
// speedup vs baseline: 1.6151x; 1.0056x over previous
#include <cuda_runtime.h>
#include <math.h>

#define BB    16
#define CINN  64
#define COUTT 64
#define M1N   32
#define M2N   32
#define KXN   64

// ---------------- scratch ----------------
__device__ float  g_Y1[BB * CINN * 256 * 64];          // [b,i,h][2ky+t]  67MB
__device__ float2 g_Xf  [BB * CINN  * KXN * M2N];
__device__ float2 g_T   [BB * COUTT * KXN * M2N];
__device__ float2 g_OutF[BB * COUTT * KXN * M2N];
__device__ float  g_Zre[BB * COUTT * 256 * 32];        // [b,o][h][ky] 33.5MB
__device__ float  g_Zim[BB * COUTT * 256 * 32];
// stationary matrices (plain fp32, split per use — locked R4 format)
__device__ float g_B1c[144 * 32];   // folded fwd W-DFT cos (re), scale 1/16
__device__ float g_B1s[128 * 32];   // folded fwd W-DFT sin (im), scale 1/16
__device__ float g_A2[128 * 512];   // fwd H-DFT, scale 1/16
__device__ float g_A5[512 * 128];   // inv H-DFT
__device__ float g_C6c[32 * 136];   // folded irfft cos
__device__ float g_C6s[32 * 136];   // folded irfft sin

// ---------------- tf32 mma helpers ----------------
__device__ __forceinline__ unsigned tf32of(float x) {
    unsigned r; asm("cvt.rna.tf32.f32 %0,%1;" : "=r"(r) : "f"(x)); return r;
}
__device__ __forceinline__ void split2(float x, unsigned& h, unsigned& l) {
    h = tf32of(x);
    l = tf32of(x - __uint_as_float(h));
}
__device__ __forceinline__ void mma1(float* c, const unsigned* a, const unsigned* b) {
    asm volatile(
        "mma.sync.aligned.m16n8k8.row.col.f32.tf32.tf32.f32 "
        "{%0,%1,%2,%3},{%4,%5,%6,%7},{%8,%9},{%0,%1,%2,%3};"
        : "+f"(c[0]), "+f"(c[1]), "+f"(c[2]), "+f"(c[3])
        : "r"(a[0]), "r"(a[1]), "r"(a[2]), "r"(a[3]), "r"(b[0]), "r"(b[1]));
}
__device__ __forceinline__ void mma3(float* c, const unsigned* ah, const unsigned* al,
                                     const unsigned* bh, const unsigned* bl) {
    mma1(c, ah, bh);
    mma1(c, al, bh);
    mma1(c, ah, bl);
}

// ---------------- single fill kernel ----------------
__global__ void __launch_bounds__(256) fill_all() {
    int idx = blockIdx.x * 256 + threadIdx.x;           // 65536 threads
    // A2 [128][512]
    {
        int row = idx >> 9, col = idx & 511;
        int kxi = row >> 1, t = row & 1, h = col >> 1, s2 = col & 1;
        int kx = (kxi < 32) ? kxi : (192 + kxi);
        float s, c; sincospif((float)((kx * h) & 255) / 128.0f, &s, &c);
        g_A2[idx] = ((t == 0) ? ((s2 == 0) ? c : s) : ((s2 == 0) ? -s : c)) * (1.0f / 16.0f);
    }
    // A5 [512][128]
    {
        int row = idx >> 7, col = idx & 127;
        int h = row >> 1, t = row & 1, kxi = col >> 1, s2 = col & 1;
        int kx = (kxi < 32) ? kxi : (192 + kxi);
        float s, c; sincospif((float)((kx * h) & 255) / 128.0f, &s, &c);
        g_A5[idx] = (t == 0) ? ((s2 == 0) ? c : -s) : ((s2 == 0) ? s : c);
    }
    // B1c [144][32]
    if (idx < 144 * 32) {
        int kk = idx >> 5, ky = idx & 31;
        float v;
        if (kk == 0)        v = 1.0f;
        else if (kk == 1)   v = (ky & 1) ? -1.0f : 1.0f;
        else if (kk <= 128) v = cospif((float)(((kk - 1) * ky) & 255) / 128.0f);
        else                v = 0.0f;
        g_B1c[idx] = v * (1.0f / 16.0f);
    }
    // B1s [128][32]
    if (idx < 128 * 32) {
        int kk = idx >> 5, ky = idx & 31;
        g_B1s[idx] = -sinpif((float)(((kk + 1) * ky) & 255) / 128.0f) * (1.0f / 16.0f);
    }
    // C6c / C6s [32][136]
    if (idx < 32 * 136) {
        int ky = idx / 136, w = idx % 136;
        float base = ((ky == 0) ? 1.0f : 2.0f) * (1.0f / 256.0f);
        g_C6c[idx] = (w <= 128) ? base * cospif((float)((ky * w) & 255) / 128.0f) : 0.0f;
        g_C6s[idx] = (w >= 1 && w <= 128 && ky >= 1)
                   ? (2.0f / 256.0f) * sinpif((float)((ky * w) & 255) / 128.0f) : 0.0f;
    }
}

// ---------------- S1 folded: per 128 rows: Yre (K=144) + Yim (K=128) GEMMs ----------------
__global__ void __launch_bounds__(256) s1_wdft(const float* __restrict__ x) {
    __shared__ float sE[128][17];      // 8.7KB folded data chunk
    __shared__ float sB[16][33];       // 2.1KB B chunk
    const int tid = threadIdx.x, warp = tid >> 5, lane = tid & 31;
    const int g = lane >> 2, tg = lane & 3;
    const int r0 = blockIdx.x * 128;
    const float* xs = x + (size_t)r0 * 256;

    // ---- GEMM-re: Yre = [x0, x128, E(1..127)] @ B1c ----
    {
        float c[4][4];
#pragma unroll
        for (int i = 0; i < 4; i++)
#pragma unroll
            for (int j = 0; j < 4; j++) c[i][j] = 0.f;

        for (int kc = 0; kc < 9; kc++) {
            __syncthreads();
            for (int i = tid; i < 128 * 16; i += 256) {
                int row = i >> 4, j = i & 15;
                int kk = kc * 16 + j;
                float v;
                if (kk == 0)        v = xs[(size_t)row * 256];
                else if (kk == 1)   v = xs[(size_t)row * 256 + 128];
                else if (kk <= 128) {
                    int w = kk - 1;
                    v = xs[(size_t)row * 256 + w] + xs[(size_t)row * 256 + 256 - w];
                } else v = 0.f;
                sE[row][j] = v;
            }
            for (int i = tid; i < 16 * 32; i += 256) {
                int k = i >> 5, n = i & 31;
                sB[k][n] = g_B1c[(kc * 16 + k) * 32 + n];
            }
            __syncthreads();
#pragma unroll
            for (int ks = 0; ks < 2; ks++) {
                unsigned ah[4], al[4];
                split2(sE[warp * 16 + g    ][ks * 8 + tg    ], ah[0], al[0]);
                split2(sE[warp * 16 + g + 8][ks * 8 + tg    ], ah[1], al[1]);
                split2(sE[warp * 16 + g    ][ks * 8 + tg + 4], ah[2], al[2]);
                split2(sE[warp * 16 + g + 8][ks * 8 + tg + 4], ah[3], al[3]);
#pragma unroll
                for (int nt = 0; nt < 4; nt++) {
                    unsigned bh[2], bl[2];
                    split2(sB[ks * 8 + tg    ][nt * 8 + g], bh[0], bl[0]);
                    split2(sB[ks * 8 + tg + 4][nt * 8 + g], bh[1], bl[1]);
                    mma3(c[nt], ah, al, bh, bl);
                }
            }
        }
#pragma unroll
        for (int nt = 0; nt < 4; nt++) {
            int row = r0 + warp * 16 + g;
            int ky0 = nt * 8 + 2 * tg;
            g_Y1[(size_t)row * 64 + 2 * ky0]           = c[nt][0];
            g_Y1[(size_t)row * 64 + 2 * (ky0 + 1)]     = c[nt][1];
            g_Y1[(size_t)(row + 8) * 64 + 2 * ky0]     = c[nt][2];
            g_Y1[(size_t)(row + 8) * 64 + 2 * (ky0 + 1)] = c[nt][3];
        }
    }

    // ---- GEMM-im: Yim = O(1..128) @ B1s ----
    {
        float c[4][4];
#pragma unroll
        for (int i = 0; i < 4; i++)
#pragma unroll
            for (int j = 0; j < 4; j++) c[i][j] = 0.f;

        for (int kc = 0; kc < 8; kc++) {
            __syncthreads();
            for (int i = tid; i < 128 * 16; i += 256) {
                int row = i >> 4, j = i & 15;
                int w = kc * 16 + j + 1;    // 1..128
                sE[row][j] = xs[(size_t)row * 256 + w] - xs[(size_t)row * 256 + ((256 - w) & 255)]
                             * ((w == 128) ? 1.0f : 1.0f);
            }
            for (int i = tid; i < 16 * 32; i += 256) {
                int k = i >> 5, n = i & 31;
                sB[k][n] = g_B1s[(kc * 16 + k) * 32 + n];
            }
            __syncthreads();
#pragma unroll
            for (int ks = 0; ks < 2; ks++) {
                unsigned ah[4], al[4];
                split2(sE[warp * 16 + g    ][ks * 8 + tg    ], ah[0], al[0]);
                split2(sE[warp * 16 + g + 8][ks * 8 + tg    ], ah[1], al[1]);
                split2(sE[warp * 16 + g    ][ks * 8 + tg + 4], ah[2], al[2]);
                split2(sE[warp * 16 + g + 8][ks * 8 + tg + 4], ah[3], al[3]);
#pragma unroll
                for (int nt = 0; nt < 4; nt++) {
                    unsigned bh[2], bl[2];
                    split2(sB[ks * 8 + tg    ][nt * 8 + g], bh[0], bl[0]);
                    split2(sB[ks * 8 + tg + 4][nt * 8 + g], bh[1], bl[1]);
                    mma3(c[nt], ah, al, bh, bl);
                }
            }
        }
#pragma unroll
        for (int nt = 0; nt < 4; nt++) {
            int row = r0 + warp * 16 + g;
            int ky0 = nt * 8 + 2 * tg;
            g_Y1[(size_t)row * 64 + 2 * ky0 + 1]           = c[nt][0];
            g_Y1[(size_t)row * 64 + 2 * (ky0 + 1) + 1]     = c[nt][1];
            g_Y1[(size_t)(row + 8) * 64 + 2 * ky0 + 1]     = c[nt][2];
            g_Y1[(size_t)(row + 8) * 64 + 2 * (ky0 + 1) + 1] = c[nt][3];
        }
    }
}

// ---------------- S2 (exact R4): Xf = A2 @ Y1slab ----------------
__global__ void __launch_bounds__(256) s2_hdft() {
    __shared__ float sA[128][33];
    __shared__ float sY[16][66];
    const int tid = threadIdx.x, warp = tid >> 5, lane = tid & 31;
    const int g = lane >> 2, tg = lane & 3;
    const int bi = blockIdx.x;

    float c[4][4];
#pragma unroll
    for (int i = 0; i < 4; i++)
#pragma unroll
        for (int j = 0; j < 4; j++) c[i][j] = 0.f;

    for (int kc = 0; kc < 16; kc++) {
        __syncthreads();
        for (int i = tid; i < 128 * 32; i += 256) {
            int row = i >> 5, col = i & 31;
            sA[row][col] = g_A2[row * 512 + kc * 32 + col];
        }
        for (int i = tid; i < 16 * 64; i += 256) {
            int h = i >> 6, cc = i & 63;
            sY[h][cc] = g_Y1[((size_t)bi * 256 + kc * 16 + h) * 64 + cc];
        }
        __syncthreads();
#pragma unroll
        for (int ks = 0; ks < 4; ks++) {
            unsigned ah[4], al[4];
            split2(sA[warp * 16 + g    ][ks * 8 + tg    ], ah[0], al[0]);
            split2(sA[warp * 16 + g + 8][ks * 8 + tg    ], ah[1], al[1]);
            split2(sA[warp * 16 + g    ][ks * 8 + tg + 4], ah[2], al[2]);
            split2(sA[warp * 16 + g + 8][ks * 8 + tg + 4], ah[3], al[3]);
            int k0 = ks * 8 + tg, k1 = k0 + 4;
#pragma unroll
            for (int nt = 0; nt < 4; nt++) {
                unsigned bh[2], bl[2];
                int n = nt * 8 + g;
                split2(sY[k0 >> 1][2 * n + (k0 & 1)], bh[0], bl[0]);
                split2(sY[k1 >> 1][2 * n + (k1 & 1)], bh[1], bl[1]);
                mma3(c[nt], ah, al, bh, bl);
            }
        }
    }
    float* xf = (float*)g_Xf + (size_t)bi * 4096;
#pragma unroll
    for (int nt = 0; nt < 4; nt++) {
        int m0 = warp * 16 + g, m1 = m0 + 8;
        int n0 = nt * 8 + 2 * tg, n1 = n0 + 1;
        xf[(m0 >> 1) * 64 + 2 * n0 + (m0 & 1)] = c[nt][0];
        xf[(m0 >> 1) * 64 + 2 * n1 + (m0 & 1)] = c[nt][1];
        xf[(m1 >> 1) * 64 + 2 * n0 + (m1 & 1)] = c[nt][2];
        xf[(m1 >> 1) * 64 + 2 * n1 + (m1 & 1)] = c[nt][3];
    }
}

// ---------------- K3a (exact R4) ----------------
__global__ void __launch_bounds__(256) k3a_mixx(const float* __restrict__ wx1,
                                                const float* __restrict__ wx2) {
    __shared__ float2 sX[CINN][M2N];
    __shared__ float2 sW[CINN][COUTT];
    const int tid = threadIdx.x;
    const int kxi = blockIdx.x, b = blockIdx.y;
    const int m = (kxi < 32) ? kxi : (kxi - 32);
    const float2* wsrc = (const float2*)((kxi < 32) ? wx1 : wx2);

    for (int idx = tid; idx < CINN * M2N; idx += 256) {
        int i = idx >> 5, k = idx & 31;
        sX[i][k] = g_Xf[((b * CINN + i) * KXN + kxi) * M2N + k];
    }
    for (int idx = tid; idx < CINN * COUTT; idx += 256) {
        int i = idx >> 6, c = idx & 63;
        sW[i][c] = wsrc[(i * COUTT + c) * M1N + m];
    }
    __syncthreads();

    const int ky = tid & 31;
    const int cb = (tid >> 5) << 3;
    float2 acc[8];
#pragma unroll
    for (int j = 0; j < 8; j++) acc[j] = make_float2(0.f, 0.f);
    for (int i = 0; i < CINN; i++) {
        float2 xv = sX[i][ky];
#pragma unroll
        for (int j = 0; j < 8; j++) {
            float2 wv = sW[i][cb + j];
            acc[j].x = fmaf(xv.x, wv.x, fmaf(-xv.y, wv.y, acc[j].x));
            acc[j].y = fmaf(xv.x, wv.y, fmaf( xv.y, wv.x, acc[j].y));
        }
    }
#pragma unroll
    for (int j = 0; j < 8; j++)
        g_T[((b * COUTT + cb + j) * KXN + kxi) * M2N + ky] = acc[j];
}

// ---------------- K3b (exact R4) ----------------
__global__ void __launch_bounds__(256) k3b_mixy(const float* __restrict__ wy) {
    __shared__ float2 sT[32][KXN];
    __shared__ float2 sWy[32][COUTT];
    const int tid = threadIdx.x;
    const int ky = blockIdx.x, b = blockIdx.y;
    const int kxi = tid & 63;
    const int ob = (tid >> 6) << 4;
    const float2* wyp = (const float2*)wy;

    float2 acc[16];
#pragma unroll
    for (int j = 0; j < 16; j++) acc[j] = make_float2(0.f, 0.f);

    for (int cb = 0; cb < COUTT; cb += 32) {
        __syncthreads();
        for (int idx = tid; idx < 32 * KXN; idx += 256) {
            int cl = idx >> 6, kk = idx & 63;
            sT[cl][kk] = g_T[((b * COUTT + cb + cl) * KXN + kk) * M2N + ky];
        }
        for (int idx = tid; idx < 32 * COUTT; idx += 256) {
            int cl = idx >> 6, o = idx & 63;
            sWy[cl][o] = wyp[((cb + cl) * COUTT + o) * M2N + ky];
        }
        __syncthreads();
        for (int cl = 0; cl < 32; cl++) {
            float2 tv = sT[cl][kxi];
#pragma unroll
            for (int j = 0; j < 16; j++) {
                float2 wv = sWy[cl][ob + j];
                acc[j].x = fmaf(tv.x, wv.x, fmaf(-tv.y, wv.y, acc[j].x));
                acc[j].y = fmaf(tv.x, wv.y, fmaf( tv.y, wv.x, acc[j].y));
            }
        }
    }
#pragma unroll
    for (int j = 0; j < 16; j++)
        g_OutF[((b * COUTT + ob + j) * KXN + kxi) * M2N + ky] = acc[j];
}

// ---------------- S5 (R4 mainloop, plane epilogue): Z = A5 @ OutFslab ----------------
__global__ void __launch_bounds__(256) s5_invh() {
    __shared__ float sA[256][17];
    __shared__ float sF[64][66];
    const int tid = threadIdx.x, warp = tid >> 5, lane = tid & 31;
    const int g = lane >> 2, tg = lane & 3;
    const int mh = blockIdx.x, bo = blockIdx.y;

    const float* outf = (const float*)g_OutF + (size_t)bo * 4096;
    for (int i = tid; i < 64 * 64; i += 256) {
        int r = i >> 6, cc = i & 63;
        sF[r][cc] = outf[r * 64 + cc];
    }

    float c[2][4][4];
#pragma unroll
    for (int a = 0; a < 2; a++)
#pragma unroll
        for (int i = 0; i < 4; i++)
#pragma unroll
            for (int j = 0; j < 4; j++) c[a][i][j] = 0.f;

    for (int kc = 0; kc < 8; kc++) {
        __syncthreads();
        for (int i = tid; i < 256 * 16; i += 256) {
            int row = i >> 4, col = i & 15;
            sA[row][col] = g_A5[(mh * 256 + row) * 128 + kc * 16 + col];
        }
        __syncthreads();
#pragma unroll
        for (int ks = 0; ks < 2; ks++) {
            int kg0 = kc * 16 + ks * 8 + tg, kg1 = kg0 + 4;
            unsigned bharr[4][2], blarr[4][2];
#pragma unroll
            for (int nt = 0; nt < 4; nt++) {
                int n = nt * 8 + g;
                split2(sF[kg0 >> 1][2 * n + (kg0 & 1)], bharr[nt][0], blarr[nt][0]);
                split2(sF[kg1 >> 1][2 * n + (kg1 & 1)], bharr[nt][1], blarr[nt][1]);
            }
#pragma unroll
            for (int mt = 0; mt < 2; mt++) {
                int r = warp * 32 + mt * 16;
                unsigned ah[4], al[4];
                split2(sA[r + g    ][ks * 8 + tg    ], ah[0], al[0]);
                split2(sA[r + g + 8][ks * 8 + tg    ], ah[1], al[1]);
                split2(sA[r + g    ][ks * 8 + tg + 4], ah[2], al[2]);
                split2(sA[r + g + 8][ks * 8 + tg + 4], ah[3], al[3]);
#pragma unroll
                for (int nt = 0; nt < 4; nt++)
                    mma3(c[mt][nt], ah, al, bharr[nt], blarr[nt]);
            }
        }
    }
    float* zre = g_Zre + (size_t)bo * 8192;
    float* zim = g_Zim + (size_t)bo * 8192;
#pragma unroll
    for (int mt = 0; mt < 2; mt++)
#pragma unroll
        for (int nt = 0; nt < 4; nt++) {
            int m0 = mh * 256 + warp * 32 + mt * 16 + g, m1 = m0 + 8;
            int n0 = nt * 8 + 2 * tg, n1 = n0 + 1;
            float* p0 = (m0 & 1) ? zim : zre;
            float* p1 = (m1 & 1) ? zim : zre;
            p0[(m0 >> 1) * 32 + n0] = c[mt][nt][0];
            p0[(m0 >> 1) * 32 + n1] = c[mt][nt][1];
            p1[(m1 >> 1) * 32 + n0] = c[mt][nt][2];
            p1[(m1 >> 1) * 32 + n1] = c[mt][nt][3];
        }
}

// ---------------- S6 folded: A = Zre@C6c, B = Zim@C6s; out[w]=A−B, out[256−w]=A+B ----------------
// dyn smem: sZre[128][33] | sZim[128][33] | sCc[32][137] | sCs[32][137]
#define S6_SMEM ((128*33*2 + 32*137*2) * 4)

__global__ void __launch_bounds__(256) s6_invw(float* __restrict__ out) {
    extern __shared__ float sm6[];
    float* sZre = sm6;                       // [128][33]
    float* sZim = sZre + 128 * 33;           // [128][33]
    float* sCc  = sZim + 128 * 33;           // [32][137]
    float* sCs  = sCc + 32 * 137;            // [32][137]
    const int tid = threadIdx.x, warp = tid >> 5, lane = tid & 31;
    const int g = lane >> 2, tg = lane & 3;
    const int mt2 = blockIdx.x, bo = blockIdx.y;

    const float* zre = g_Zre + (size_t)bo * 8192 + mt2 * 128 * 32;
    const float* zim = g_Zim + (size_t)bo * 8192 + mt2 * 128 * 32;
    for (int i = tid; i < 128 * 32; i += 256) {
        int r = i >> 5, cc = i & 31;
        sZre[r * 33 + cc] = zre[i];
        sZim[r * 33 + cc] = zim[i];
    }
    for (int i = tid; i < 32 * 136; i += 256) {
        int k = i / 136, n = i % 136;
        sCc[k * 137 + n] = g_C6c[i];
        sCs[k * 137 + n] = g_C6s[i];
    }
    __syncthreads();

    // preload A-operand fragments (K=32: 4 ksteps), re and im
    unsigned aReh[4][4], aRel[4][4], aImh[4][4], aIml[4][4];
    {
        int r0 = warp * 16 + g, r1 = r0 + 8;
#pragma unroll
        for (int ks = 0; ks < 4; ks++) {
            int k0 = ks * 8 + tg, k1 = k0 + 4;
            split2(sZre[r0 * 33 + k0], aReh[ks][0], aRel[ks][0]);
            split2(sZre[r1 * 33 + k0], aReh[ks][1], aRel[ks][1]);
            split2(sZre[r0 * 33 + k1], aReh[ks][2], aRel[ks][2]);
            split2(sZre[r1 * 33 + k1], aReh[ks][3], aRel[ks][3]);
            split2(sZim[r0 * 33 + k0], aImh[ks][0], aIml[ks][0]);
            split2(sZim[r1 * 33 + k0], aImh[ks][1], aIml[ks][1]);
            split2(sZim[r0 * 33 + k1], aImh[ks][2], aIml[ks][2]);
            split2(sZim[r1 * 33 + k1], aImh[ks][3], aIml[ks][3]);
        }
    }

    float* orow = out + (size_t)bo * 65536 + (size_t)mt2 * 128 * 256;
    const int m = warp * 16 + g;

#pragma unroll 1
    for (int nt = 0; nt < 17; nt++) {
        float accA[4] = {0.f, 0.f, 0.f, 0.f};
        float accB[4] = {0.f, 0.f, 0.f, 0.f};
#pragma unroll
        for (int ks = 0; ks < 4; ks++) {
            unsigned bh[2], bl[2];
            split2(sCc[(ks * 8 + tg) * 137 + nt * 8 + g], bh[0], bl[0]);
            split2(sCc[(ks * 8 + tg + 4) * 137 + nt * 8 + g], bh[1], bl[1]);
            mma3(accA, aReh[ks], aRel[ks], bh, bl);
            split2(sCs[(ks * 8 + tg) * 137 + nt * 8 + g], bh[0], bl[0]);
            split2(sCs[(ks * 8 + tg + 4) * 137 + nt * 8 + g], bh[1], bl[1]);
            mma3(accB, aImh[ks], aIml[ks], bh, bl);
        }
        int w0 = nt * 8 + 2 * tg;
#pragma unroll
        for (int p = 0; p < 2; p++) {
            int w = w0 + p;
            if (w > 128) continue;           // only trims nt==16 tail
            float v0 = accA[p]     - accB[p];
            float v1 = accA[p + 2] - accB[p + 2];
            orow[m * 256 + w]       = v0;
            orow[(m + 8) * 256 + w] = v1;
            if (w >= 1 && w <= 127) {
                orow[m * 256 + 256 - w]       = accA[p]     + accB[p];
                orow[(m + 8) * 256 + 256 - w] = accA[p + 2] + accB[p + 2];
            }
        }
    }
}

extern "C" void kernel_launch(void* const* d_in, const int* in_sizes, int n_in,
                              void* d_out, int out_size) {
    const float* x   = (const float*)d_in[0];
    const float* wx1 = (const float*)d_in[1];
    const float* wx2 = (const float*)d_in[2];
    const float* wy  = (const float*)d_in[3];
    float* out = (float*)d_out;

    cudaFuncSetAttribute(s6_invw, cudaFuncAttributeMaxDynamicSharedMemorySize, S6_SMEM);

    fill_all<<<256, 256>>>();
    s1_wdft<<<2048, 256>>>(x);                 // folded W-DFT (re + im GEMMs)
    s2_hdft<<<1024, 256>>>();                  // H-DFT
    k3a_mixx<<<dim3(KXN, BB), 256>>>(wx1, wx2);
    k3b_mixy<<<dim3(M2N, BB), 256>>>(wy);
    s5_invh<<<dim3(2, 1024), 256>>>();         // inverse H (plane epilogue)
    s6_invw<<<dim3(2, 1024), 256, S6_SMEM>>>(out);  // folded irfft-W
}

// round 13
// speedup vs baseline: 1.7438x; 1.0797x over previous
#include <cuda_runtime.h>
#include <cuda_bf16.h>
#include <math.h>
#include <stdint.h>

#define BB 16
#define CN 64

// ---- scratch ----
__device__ unsigned g_Y1h[BB*CN*256*32], g_Y1l[BB*CN*256*32];   // packed bf16x2 (re? no: (evenK,oddK)) planes
__device__ float2   g_Xf [BB*CN*64*32];
__device__ float2   g_T  [BB*CN*64*32];
__device__ unsigned g_OFh[BB*CN*64*32], g_OFl[BB*CN*64*32];     // OutF packed (re,im)
__device__ float    g_Z  [BB*CN*256*64];
// stationary packed planes
__device__ unsigned g_B1ph[64*128],  g_B1pl[64*128];    // [n][k2] fwd W-DFT, 1/16
__device__ unsigned g_A2ph[128*256], g_A2pl[128*256];   // [m][k2] fwd H-DFT, 1/16
__device__ unsigned g_A5ph[512*64],  g_A5pl[512*64];    // [m][k2] inv H-DFT
__device__ unsigned g_C6ph[256*32],  g_C6pl[256*32];    // [n][k2] irfft, 1/256

__device__ __forceinline__ void packsplit(float a, float b, unsigned& h, unsigned& l) {
    __nv_bfloat162 hv = __floats2bfloat162_rn(a, b);
    __nv_bfloat162 lv = __floats2bfloat162_rn(a - __bfloat162float(hv.x),
                                              b - __bfloat162float(hv.y));
    h = *(unsigned*)&hv; l = *(unsigned*)&lv;
}
__device__ __forceinline__ void mmab(float* c, const unsigned* a, const unsigned* b) {
    asm volatile(
        "mma.sync.aligned.m16n8k16.row.col.f32.bf16.bf16.f32 "
        "{%0,%1,%2,%3},{%4,%5,%6,%7},{%8,%9},{%0,%1,%2,%3};"
        : "+f"(c[0]), "+f"(c[1]), "+f"(c[2]), "+f"(c[3])
        : "r"(a[0]), "r"(a[1]), "r"(a[2]), "r"(a[3]), "r"(b[0]), "r"(b[1]));
}
__device__ __forceinline__ void mma3b(float* c, const unsigned* ah, const unsigned* al,
                                      const unsigned* bh, const unsigned* bl) {
    mmab(c, ah, bh); mmab(c, al, bh); mmab(c, ah, bl);
}

// ---- fill ----
__global__ void __launch_bounds__(256) fill_all() {
    int idx = blockIdx.x * 256 + threadIdx.x;   // 32768 threads
    {   // A2p [128][256]
        int m = idx >> 8, k2 = idx & 255;
        int kxi = m >> 1, t = m & 1, kx = (kxi < 32) ? kxi : 192 + kxi;
        float s, c; sincospif((float)((kx * k2) & 255) / 128.0f, &s, &c);
        float v0 = (t ? -s : c) * (1.0f/16.0f), v1 = (t ? c : s) * (1.0f/16.0f);
        packsplit(v0, v1, g_A2ph[idx], g_A2pl[idx]);
    }
    {   // A5p [512][64]
        int m = idx >> 6, k2 = idx & 63;
        int h = m >> 1, t = m & 1, kx = (k2 < 32) ? k2 : 192 + k2;
        float s, c; sincospif((float)((kx * h) & 255) / 128.0f, &s, &c);
        float v0 = (t ? s : c), v1 = (t ? c : -s);
        packsplit(v0, v1, g_A5ph[idx], g_A5pl[idx]);
    }
    if (idx < 8192) {   // B1p [64][128]
        int n = idx >> 7, k2 = idx & 127;
        int ky = n >> 1, t = n & 1;
        float s0, c0, s1, c1;
        sincospif((float)(((2*k2) * ky) & 255) / 128.0f, &s0, &c0);
        sincospif((float)(((2*k2+1) * ky) & 255) / 128.0f, &s1, &c1);
        float v0 = (t ? -s0 : c0) * (1.0f/16.0f), v1 = (t ? -s1 : c1) * (1.0f/16.0f);
        packsplit(v0, v1, g_B1ph[idx], g_B1pl[idx]);
    }
    if (idx < 8192) {   // C6p [256][32]
        int w = idx >> 5, ky = idx & 31;
        float s, c; sincospif((float)((ky * w) & 255) / 128.0f, &s, &c);
        float base = ((ky == 0) ? 1.0f : 2.0f) * (1.0f/256.0f);
        float v0 = base * c, v1 = (ky == 0) ? 0.0f : -base * s;
        packsplit(v0, v1, g_C6ph[idx], g_C6pl[idx]);
    }
}

// ---- S1: Y1 = x @ B1 (M=128/CTA, K=256, N=64) ----
__global__ void __launch_bounds__(256) s1_wdft(const float* __restrict__ x) {
    __shared__ unsigned sXh[128][17], sXl[128][17], sBh[64][17], sBl[64][17];
    const int tid = threadIdx.x, warp = tid >> 5, lane = tid & 31;
    const int g = lane >> 2, tg = lane & 3;
    const size_t r0 = (size_t)blockIdx.x * 128;
    float c[8][4];
#pragma unroll
    for (int i = 0; i < 8; i++) { c[i][0]=c[i][1]=c[i][2]=c[i][3]=0.f; }

    for (int kc = 0; kc < 8; kc++) {
        __syncthreads();
        for (int i = tid; i < 2048; i += 256) {
            int row = i >> 4, col = i & 15;
            float2 v = *(const float2*)&x[(r0 + row) * 256 + kc * 32 + 2 * col];
            packsplit(v.x, v.y, sXh[row][col], sXl[row][col]);
        }
        for (int i = tid; i < 1024; i += 256) {
            int n = i >> 4, col = i & 15;
            sBh[n][col] = g_B1ph[n * 128 + kc * 16 + col];
            sBl[n][col] = g_B1pl[n * 128 + kc * 16 + col];
        }
        __syncthreads();
#pragma unroll
        for (int ks = 0; ks < 2; ks++) {
            int r = warp * 16 + g, k0 = ks * 8 + tg;
            unsigned ah[4] = {sXh[r][k0], sXh[r+8][k0], sXh[r][k0+4], sXh[r+8][k0+4]};
            unsigned al[4] = {sXl[r][k0], sXl[r+8][k0], sXl[r][k0+4], sXl[r+8][k0+4]};
#pragma unroll
            for (int nt = 0; nt < 8; nt++) {
                int n = nt * 8 + g;
                unsigned bh[2] = {sBh[n][k0], sBh[n][k0+4]};
                unsigned bl[2] = {sBl[n][k0], sBl[n][k0+4]};
                mma3b(c[nt], ah, al, bh, bl);
            }
        }
    }
#pragma unroll
    for (int nt = 0; nt < 8; nt++) {
        size_t m = r0 + warp * 16 + g;
        int ky = nt * 4 + tg;
        unsigned h0, l0, h1, l1;
        packsplit(c[nt][0], c[nt][1], h0, l0);
        packsplit(c[nt][2], c[nt][3], h1, l1);
        g_Y1h[m * 32 + ky] = h0;       g_Y1l[m * 32 + ky] = l0;
        g_Y1h[(m + 8) * 32 + ky] = h1; g_Y1l[(m + 8) * 32 + ky] = l1;
    }
}

// ---- S2: Xf = A2 @ Y1slab (M=128, K=512, N=32) ----
__global__ void __launch_bounds__(256) s2_hdft() {
    __shared__ unsigned sAh[128][17], sAl[128][17], sYh[16][33], sYl[16][33];
    const int tid = threadIdx.x, warp = tid >> 5, lane = tid & 31;
    const int g = lane >> 2, tg = lane & 3;
    const int bi = blockIdx.x;
    float c[4][4];
#pragma unroll
    for (int i = 0; i < 4; i++) { c[i][0]=c[i][1]=c[i][2]=c[i][3]=0.f; }

    for (int kc = 0; kc < 16; kc++) {
        __syncthreads();
        for (int i = tid; i < 2048; i += 256) {
            int row = i >> 4, col = i & 15;
            sAh[row][col] = g_A2ph[row * 256 + kc * 16 + col];
            sAl[row][col] = g_A2pl[row * 256 + kc * 16 + col];
        }
        for (int i = tid; i < 512; i += 256) {
            int hl = i >> 5, ky = i & 31;
            size_t src = ((size_t)bi * 256 + kc * 16 + hl) * 32 + ky;
            sYh[hl][ky] = g_Y1h[src];
            sYl[hl][ky] = g_Y1l[src];
        }
        __syncthreads();
#pragma unroll
        for (int ks = 0; ks < 2; ks++) {
            int r = warp * 16 + g, k0 = ks * 8 + tg;
            unsigned ah[4] = {sAh[r][k0], sAh[r+8][k0], sAh[r][k0+4], sAh[r+8][k0+4]};
            unsigned al[4] = {sAl[r][k0], sAl[r+8][k0], sAl[r][k0+4], sAl[r+8][k0+4]};
#pragma unroll
            for (int nt = 0; nt < 4; nt++) {
                int n = nt * 8 + g;
                unsigned bh[2] = {sYh[k0][n], sYh[k0+4][n]};
                unsigned bl[2] = {sYl[k0][n], sYl[k0+4][n]};
                mma3b(c[nt], ah, al, bh, bl);
            }
        }
    }
    float* xf = (float*)g_Xf + (size_t)bi * 4096;
#pragma unroll
    for (int nt = 0; nt < 4; nt++) {
        int m0 = warp * 16 + g, m1 = m0 + 8;
        int n0 = nt * 8 + 2 * tg, n1 = n0 + 1;
        xf[(m0 >> 1) * 64 + 2 * n0 + (m0 & 1)] = c[nt][0];
        xf[(m0 >> 1) * 64 + 2 * n1 + (m0 & 1)] = c[nt][1];
        xf[(m1 >> 1) * 64 + 2 * n0 + (m1 & 1)] = c[nt][2];
        xf[(m1 >> 1) * 64 + 2 * n1 + (m1 & 1)] = c[nt][3];
    }
}

// ---- K3a (FFMA, R4): t = sum_i Xf * w ----
__global__ void __launch_bounds__(256) k3a_mixx(const float* __restrict__ wx1,
                                                const float* __restrict__ wx2) {
    __shared__ float2 sX[64][32];
    __shared__ float2 sW[64][64];
    const int tid = threadIdx.x;
    const int kxi = blockIdx.x, b = blockIdx.y;
    const int m = (kxi < 32) ? kxi : (kxi - 32);
    const float2* wsrc = (const float2*)((kxi < 32) ? wx1 : wx2);

    for (int idx = tid; idx < 2048; idx += 256) {
        int i = idx >> 5, k = idx & 31;
        sX[i][k] = g_Xf[((b * 64 + i) * 64 + kxi) * 32 + k];
    }
    for (int idx = tid; idx < 4096; idx += 256) {
        int i = idx >> 6, c = idx & 63;
        sW[i][c] = wsrc[(i * 64 + c) * 32 + m];
    }
    __syncthreads();
    const int ky = tid & 31, cb = (tid >> 5) << 3;
    float2 acc[8];
#pragma unroll
    for (int j = 0; j < 8; j++) acc[j] = make_float2(0.f, 0.f);
    for (int i = 0; i < 64; i++) {
        float2 xv = sX[i][ky];
#pragma unroll
        for (int j = 0; j < 8; j++) {
            float2 wv = sW[i][cb + j];
            acc[j].x = fmaf(xv.x, wv.x, fmaf(-xv.y, wv.y, acc[j].x));
            acc[j].y = fmaf(xv.x, wv.y, fmaf( xv.y, wv.x, acc[j].y));
        }
    }
#pragma unroll
    for (int j = 0; j < 8; j++)
        g_T[((b * 64 + cb + j) * 64 + kxi) * 32 + ky] = acc[j];
}

// ---- K3b (FFMA, packed epilogue): OutF = sum_c t * wy ----
__global__ void __launch_bounds__(256) k3b_mixy(const float* __restrict__ wy) {
    __shared__ float2 sT[32][64];
    __shared__ float2 sWy[32][64];
    const int tid = threadIdx.x;
    const int ky = blockIdx.x, b = blockIdx.y;
    const int kxi = tid & 63, ob = (tid >> 6) << 4;
    const float2* wyp = (const float2*)wy;
    float2 acc[16];
#pragma unroll
    for (int j = 0; j < 16; j++) acc[j] = make_float2(0.f, 0.f);

    for (int cb = 0; cb < 64; cb += 32) {
        __syncthreads();
        for (int idx = tid; idx < 2048; idx += 256) {
            int cl = idx >> 6, kk = idx & 63;
            sT[cl][kk] = g_T[((b * 64 + cb + cl) * 64 + kk) * 32 + ky];
        }
        for (int idx = tid; idx < 2048; idx += 256) {
            int cl = idx >> 6, o = idx & 63;
            sWy[cl][o] = wyp[((cb + cl) * 64 + o) * 32 + ky];
        }
        __syncthreads();
        for (int cl = 0; cl < 32; cl++) {
            float2 tv = sT[cl][kxi];
#pragma unroll
            for (int j = 0; j < 16; j++) {
                float2 wv = sWy[cl][ob + j];
                acc[j].x = fmaf(tv.x, wv.x, fmaf(-tv.y, wv.y, acc[j].x));
                acc[j].y = fmaf(tv.x, wv.y, fmaf( tv.y, wv.x, acc[j].y));
            }
        }
    }
#pragma unroll
    for (int j = 0; j < 16; j++) {
        unsigned h, l;
        packsplit(acc[j].x, acc[j].y, h, l);
        size_t o = ((size_t)(b * 64 + ob + j) * 64 + kxi) * 32 + ky;
        g_OFh[o] = h; g_OFl[o] = l;
    }
}

// ---- S5: Z = A5 @ OutF (M=512, K=128, N=32) ----
__global__ void __launch_bounds__(256) s5_invh() {
    __shared__ unsigned sAh[256][9], sAl[256][9], sFh[64][33], sFl[64][33];
    const int tid = threadIdx.x, warp = tid >> 5, lane = tid & 31;
    const int g = lane >> 2, tg = lane & 3;
    const int mh = blockIdx.x, bo = blockIdx.y;

    for (int i = tid; i < 2048; i += 256) {
        int kxi = i >> 5, ky = i & 31;
        sFh[kxi][ky] = g_OFh[(size_t)bo * 2048 + i];
        sFl[kxi][ky] = g_OFl[(size_t)bo * 2048 + i];
    }
    float c[2][4][4];
#pragma unroll
    for (int a = 0; a < 2; a++)
#pragma unroll
        for (int i = 0; i < 4; i++) { c[a][i][0]=c[a][i][1]=c[a][i][2]=c[a][i][3]=0.f; }

    for (int kc = 0; kc < 8; kc++) {
        __syncthreads();
        for (int i = tid; i < 2048; i += 256) {
            int row = i >> 3, col = i & 7;
            sAh[row][col] = g_A5ph[(mh * 256 + row) * 64 + kc * 8 + col];
            sAl[row][col] = g_A5pl[(mh * 256 + row) * 64 + kc * 8 + col];
        }
        __syncthreads();
        unsigned bha[4][2], bla[4][2];
#pragma unroll
        for (int nt = 0; nt < 4; nt++) {
            int n = nt * 8 + g;
            bha[nt][0] = sFh[kc*8+tg][n]; bha[nt][1] = sFh[kc*8+tg+4][n];
            bla[nt][0] = sFl[kc*8+tg][n]; bla[nt][1] = sFl[kc*8+tg+4][n];
        }
#pragma unroll
        for (int mt = 0; mt < 2; mt++) {
            int r = warp * 32 + mt * 16 + g;
            unsigned ah[4] = {sAh[r][tg], sAh[r+8][tg], sAh[r][tg+4], sAh[r+8][tg+4]};
            unsigned al[4] = {sAl[r][tg], sAl[r+8][tg], sAl[r][tg+4], sAl[r+8][tg+4]};
#pragma unroll
            for (int nt = 0; nt < 4; nt++)
                mma3b(c[mt][nt], ah, al, bha[nt], bla[nt]);
        }
    }
    float* z = g_Z + (size_t)bo * 16384;
#pragma unroll
    for (int mt = 0; mt < 2; mt++)
#pragma unroll
        for (int nt = 0; nt < 4; nt++) {
            int m0 = mh * 256 + warp * 32 + mt * 16 + g, m1 = m0 + 8;
            int n0 = nt * 8 + 2 * tg, n1 = n0 + 1;
            z[(m0 >> 1) * 64 + 2 * n0 + (m0 & 1)] = c[mt][nt][0];
            z[(m0 >> 1) * 64 + 2 * n1 + (m0 & 1)] = c[mt][nt][1];
            z[(m1 >> 1) * 64 + 2 * n0 + (m1 & 1)] = c[mt][nt][2];
            z[(m1 >> 1) * 64 + 2 * n1 + (m1 & 1)] = c[mt][nt][3];
        }
}

// ---- S6: out = Z @ C6 (M=256, K=64, N=256) ----
__global__ void __launch_bounds__(256) s6_invw(float* __restrict__ out) {
    __shared__ unsigned sZh[128][17], sZl[128][17], sCh[128][17], sCl[128][17];
    const int tid = threadIdx.x, warp = tid >> 5, lane = tid & 31;
    const int g = lane >> 2, tg = lane & 3;
    const int mt2 = blockIdx.x, nt2 = blockIdx.y, bo = blockIdx.z;
    float c[16][4];
#pragma unroll
    for (int i = 0; i < 16; i++) { c[i][0]=c[i][1]=c[i][2]=c[i][3]=0.f; }

    const float* z = g_Z + (size_t)bo * 16384;
    for (int kc = 0; kc < 2; kc++) {
        __syncthreads();
        for (int i = tid; i < 2048; i += 256) {
            int row = i >> 4, col = i & 15;
            float2 zv = *(const float2*)&z[(mt2 * 128 + row) * 64 + kc * 32 + 2 * col];
            packsplit(zv.x, zv.y, sZh[row][col], sZl[row][col]);
        }
        for (int i = tid; i < 2048; i += 256) {
            int nl = i >> 4, col = i & 15;
            sCh[nl][col] = g_C6ph[(nt2 * 128 + nl) * 32 + kc * 16 + col];
            sCl[nl][col] = g_C6pl[(nt2 * 128 + nl) * 32 + kc * 16 + col];
        }
        __syncthreads();
#pragma unroll
        for (int ks = 0; ks < 2; ks++) {
            int r = warp * 16 + g, k0 = ks * 8 + tg;
            unsigned ah[4] = {sZh[r][k0], sZh[r+8][k0], sZh[r][k0+4], sZh[r+8][k0+4]};
            unsigned al[4] = {sZl[r][k0], sZl[r+8][k0], sZl[r][k0+4], sZl[r+8][k0+4]};
#pragma unroll
            for (int nt = 0; nt < 16; nt++) {
                int n = nt * 8 + g;
                unsigned bh[2] = {sCh[n][k0], sCh[n][k0+4]};
                unsigned bl[2] = {sCl[n][k0], sCl[n][k0+4]};
                mma3b(c[nt], ah, al, bh, bl);
            }
        }
    }
    float* orow = out + (size_t)bo * 65536;
#pragma unroll
    for (int nt = 0; nt < 16; nt++) {
        int h = mt2 * 128 + warp * 16 + g;
        int w = nt2 * 128 + nt * 8 + 2 * tg;
        *(float2*)&orow[(h)     * 256 + w] = make_float2(c[nt][0], c[nt][1]);
        *(float2*)&orow[(h + 8) * 256 + w] = make_float2(c[nt][2], c[nt][3]);
    }
}

extern "C" void kernel_launch(void* const* d_in, const int* in_sizes, int n_in,
                              void* d_out, int out_size) {
    const float* x   = (const float*)d_in[0];
    const float* wx1 = (const float*)d_in[1];
    const float* wx2 = (const float*)d_in[2];
    const float* wy  = (const float*)d_in[3];
    float* out = (float*)d_out;

    fill_all<<<128, 256>>>();
    s1_wdft<<<2048, 256>>>(x);
    s2_hdft<<<1024, 256>>>();
    k3a_mixx<<<dim3(64, BB), 256>>>(wx1, wx2);
    k3b_mixy<<<dim3(32, BB), 256>>>(wy);
    s5_invh<<<dim3(2, 1024), 256>>>();
    s6_invw<<<dim3(2, 2, 1024), 256>>>(out);
}

// round 14
// speedup vs baseline: 1.8423x; 1.0565x over previous
#include <cuda_runtime.h>
#include <cuda_bf16.h>
#include <math.h>
#include <stdint.h>

#define BB 16
#define CN 64

// ---- scratch ----
__device__ unsigned g_Y1h[BB*CN*256*32], g_Y1l[BB*CN*256*32];
__device__ float2   g_Xf [BB*CN*64*32];
__device__ float2   g_T  [BB*CN*64*32];          // [b][kxi][ky][c] float2
__device__ unsigned g_OFh[BB*CN*64*32], g_OFl[BB*CN*64*32];
__device__ float    g_Z  [BB*CN*256*64];
// stationary packed planes (bf16 hi/lo as bf16x2 words)
__device__ unsigned g_B1ph[64*128],  g_B1pl[64*128];
__device__ unsigned g_A2ph[128*256], g_A2pl[128*256];
__device__ unsigned g_A5ph[512*64],  g_A5pl[512*64];
__device__ unsigned g_C6ph[256*32],  g_C6pl[256*32];
// packed complex weights: WX [m=kxi][n=2c+t][k2=i], WY [ky][n=2o+t][k2=c]
__device__ unsigned g_WXh[64*128*64], g_WXl[64*128*64];
__device__ unsigned g_WYh[32*128*64], g_WYl[32*128*64];

__device__ __forceinline__ void packsplit(float a, float b, unsigned& h, unsigned& l) {
    __nv_bfloat162 hv = __floats2bfloat162_rn(a, b);
    __nv_bfloat162 lv = __floats2bfloat162_rn(a - __bfloat162float(hv.x),
                                              b - __bfloat162float(hv.y));
    h = *(unsigned*)&hv; l = *(unsigned*)&lv;
}
__device__ __forceinline__ void mmab(float* c, const unsigned* a, const unsigned* b) {
    asm volatile(
        "mma.sync.aligned.m16n8k16.row.col.f32.bf16.bf16.f32 "
        "{%0,%1,%2,%3},{%4,%5,%6,%7},{%8,%9},{%0,%1,%2,%3};"
        : "+f"(c[0]), "+f"(c[1]), "+f"(c[2]), "+f"(c[3])
        : "r"(a[0]), "r"(a[1]), "r"(a[2]), "r"(a[3]), "r"(b[0]), "r"(b[1]));
}
__device__ __forceinline__ void mma3b(float* c, const unsigned* ah, const unsigned* al,
                                      const unsigned* bh, const unsigned* bl) {
    mmab(c, ah, bh); mmab(c, al, bh); mmab(c, ah, bl);
}

// ---- fills ----
__global__ void __launch_bounds__(256) fill_all() {
    int idx = blockIdx.x * 256 + threadIdx.x;   // 32768
    {   int m = idx >> 8, k2 = idx & 255;
        int kxi = m >> 1, t = m & 1, kx = (kxi < 32) ? kxi : 192 + kxi;
        float s, c; sincospif((float)((kx * k2) & 255) / 128.0f, &s, &c);
        packsplit((t ? -s : c) * (1.0f/16.0f), (t ? c : s) * (1.0f/16.0f),
                  g_A2ph[idx], g_A2pl[idx]);
    }
    {   int m = idx >> 6, k2 = idx & 63;
        int h = m >> 1, t = m & 1, kx = (k2 < 32) ? k2 : 192 + k2;
        float s, c; sincospif((float)((kx * h) & 255) / 128.0f, &s, &c);
        packsplit((t ? s : c), (t ? c : -s), g_A5ph[idx], g_A5pl[idx]);
    }
    if (idx < 8192) {
        int n = idx >> 7, k2 = idx & 127;
        int ky = n >> 1, t = n & 1;
        float s0, c0, s1, c1;
        sincospif((float)(((2*k2) * ky) & 255) / 128.0f, &s0, &c0);
        sincospif((float)(((2*k2+1) * ky) & 255) / 128.0f, &s1, &c1);
        packsplit((t ? -s0 : c0) * (1.0f/16.0f), (t ? -s1 : c1) * (1.0f/16.0f),
                  g_B1ph[idx], g_B1pl[idx]);
    }
    if (idx < 8192) {
        int w = idx >> 5, ky = idx & 31;
        float s, c; sincospif((float)((ky * w) & 255) / 128.0f, &s, &c);
        float base = ((ky == 0) ? 1.0f : 2.0f) * (1.0f/256.0f);
        packsplit(base * c, (ky == 0) ? 0.0f : -base * s, g_C6ph[idx], g_C6pl[idx]);
    }
}
__global__ void __launch_bounds__(256) fill_w(const float* __restrict__ wx1,
                                              const float* __restrict__ wx2,
                                              const float* __restrict__ wy) {
    int idx = blockIdx.x * 256 + threadIdx.x;   // 786432
    if (idx < 524288) {
        int k2 = idx & 63, n = (idx >> 6) & 127, m = idx >> 13;
        const float2* src = (const float2*)((m < 32) ? wx1 : wx2);
        float2 w = src[(k2 * 64 + (n >> 1)) * 32 + (m & 31)];
        float v0 = (n & 1) ? w.y : w.x;
        float v1 = (n & 1) ? w.x : -w.y;
        packsplit(v0, v1, g_WXh[idx], g_WXl[idx]);
    } else {
        int r = idx - 524288;
        int k2 = r & 63, n = (r >> 6) & 127;
        float2 w = ((const float2*)wy)[(k2 * 64 + (n >> 1)) * 32 + (r >> 13)];
        float v0 = (n & 1) ? w.y : w.x;
        float v1 = (n & 1) ? w.x : -w.y;
        packsplit(v0, v1, g_WYh[r], g_WYl[r]);
    }
}

// ---- S1: Y1 = x @ B1 (unchanged R12) ----
__global__ void __launch_bounds__(256) s1_wdft(const float* __restrict__ x) {
    __shared__ unsigned sXh[128][17], sXl[128][17], sBh[64][17], sBl[64][17];
    const int tid = threadIdx.x, warp = tid >> 5, lane = tid & 31;
    const int g = lane >> 2, tg = lane & 3;
    const size_t r0 = (size_t)blockIdx.x * 128;
    float c[8][4];
#pragma unroll
    for (int i = 0; i < 8; i++) { c[i][0]=c[i][1]=c[i][2]=c[i][3]=0.f; }
    for (int kc = 0; kc < 8; kc++) {
        __syncthreads();
        for (int i = tid; i < 2048; i += 256) {
            int row = i >> 4, col = i & 15;
            float2 v = *(const float2*)&x[(r0 + row) * 256 + kc * 32 + 2 * col];
            packsplit(v.x, v.y, sXh[row][col], sXl[row][col]);
        }
        for (int i = tid; i < 1024; i += 256) {
            int n = i >> 4, col = i & 15;
            sBh[n][col] = g_B1ph[n * 128 + kc * 16 + col];
            sBl[n][col] = g_B1pl[n * 128 + kc * 16 + col];
        }
        __syncthreads();
#pragma unroll
        for (int ks = 0; ks < 2; ks++) {
            int r = warp * 16 + g, k0 = ks * 8 + tg;
            unsigned ah[4] = {sXh[r][k0], sXh[r+8][k0], sXh[r][k0+4], sXh[r+8][k0+4]};
            unsigned al[4] = {sXl[r][k0], sXl[r+8][k0], sXl[r][k0+4], sXl[r+8][k0+4]};
#pragma unroll
            for (int nt = 0; nt < 8; nt++) {
                int n = nt * 8 + g;
                unsigned bh[2] = {sBh[n][k0], sBh[n][k0+4]};
                unsigned bl[2] = {sBl[n][k0], sBl[n][k0+4]};
                mma3b(c[nt], ah, al, bh, bl);
            }
        }
    }
#pragma unroll
    for (int nt = 0; nt < 8; nt++) {
        size_t m = r0 + warp * 16 + g;
        int ky = nt * 4 + tg;
        unsigned h0, l0, h1, l1;
        packsplit(c[nt][0], c[nt][1], h0, l0);
        packsplit(c[nt][2], c[nt][3], h1, l1);
        g_Y1h[m * 32 + ky] = h0;       g_Y1l[m * 32 + ky] = l0;
        g_Y1h[(m + 8) * 32 + ky] = h1; g_Y1l[(m + 8) * 32 + ky] = l1;
    }
}

// ---- S2: Xf = A2 @ Y1slab (unchanged R12) ----
__global__ void __launch_bounds__(256) s2_hdft() {
    __shared__ unsigned sAh[128][17], sAl[128][17], sYh[16][33], sYl[16][33];
    const int tid = threadIdx.x, warp = tid >> 5, lane = tid & 31;
    const int g = lane >> 2, tg = lane & 3;
    const int bi = blockIdx.x;
    float c[4][4];
#pragma unroll
    for (int i = 0; i < 4; i++) { c[i][0]=c[i][1]=c[i][2]=c[i][3]=0.f; }
    for (int kc = 0; kc < 16; kc++) {
        __syncthreads();
        for (int i = tid; i < 2048; i += 256) {
            int row = i >> 4, col = i & 15;
            sAh[row][col] = g_A2ph[row * 256 + kc * 16 + col];
            sAl[row][col] = g_A2pl[row * 256 + kc * 16 + col];
        }
        for (int i = tid; i < 512; i += 256) {
            int hl = i >> 5, ky = i & 31;
            size_t src = ((size_t)bi * 256 + kc * 16 + hl) * 32 + ky;
            sYh[hl][ky] = g_Y1h[src];
            sYl[hl][ky] = g_Y1l[src];
        }
        __syncthreads();
#pragma unroll
        for (int ks = 0; ks < 2; ks++) {
            int r = warp * 16 + g, k0 = ks * 8 + tg;
            unsigned ah[4] = {sAh[r][k0], sAh[r+8][k0], sAh[r][k0+4], sAh[r+8][k0+4]};
            unsigned al[4] = {sAl[r][k0], sAl[r+8][k0], sAl[r][k0+4], sAl[r+8][k0+4]};
#pragma unroll
            for (int nt = 0; nt < 4; nt++) {
                int n = nt * 8 + g;
                unsigned bh[2] = {sYh[k0][n], sYh[k0+4][n]};
                unsigned bl[2] = {sYl[k0][n], sYl[k0+4][n]};
                mma3b(c[nt], ah, al, bh, bl);
            }
        }
    }
    float* xf = (float*)g_Xf + (size_t)bi * 4096;
#pragma unroll
    for (int nt = 0; nt < 4; nt++) {
        int m0 = warp * 16 + g, m1 = m0 + 8;
        int n0 = nt * 8 + 2 * tg, n1 = n0 + 1;
        xf[(m0 >> 1) * 64 + 2 * n0 + (m0 & 1)] = c[nt][0];
        xf[(m0 >> 1) * 64 + 2 * n1 + (m0 & 1)] = c[nt][1];
        xf[(m1 >> 1) * 64 + 2 * n0 + (m1 & 1)] = c[nt][2];
        xf[(m1 >> 1) * 64 + 2 * n1 + (m1 & 1)] = c[nt][3];
    }
}

// ---- K3a (MMA): per (kxi, 4b): T[ky][c] = X @ WX, M=32 N=128 K=128 ----
#define K3A_SMEM ((2*32*68 + 2*128*68) * 4)
__global__ void __launch_bounds__(256) k3a_mma() {
    extern __shared__ unsigned sm[];
    unsigned* sAh = sm;
    unsigned* sAl = sAh + 32*68;
    unsigned* sBh = sAl + 32*68;
    unsigned* sBl = sBh + 128*68;
    const int tid = threadIdx.x, warp = tid >> 5, lane = tid & 31;
    const int g = lane >> 2, tg = lane & 3;
    const int kxi = blockIdx.x, bg = blockIdx.y;
    const int mt = warp >> 2, ng = warp & 3;

    for (int i = tid; i < 8192; i += 256) {
        int n = i >> 6, k2 = i & 63;
        sBh[n*68 + k2] = g_WXh[((size_t)kxi*128 + n)*64 + k2];
        sBl[n*68 + k2] = g_WXl[((size_t)kxi*128 + n)*64 + k2];
    }
    const float* xf = (const float*)g_Xf;
    for (int bb = 0; bb < 4; bb++) {
        int b = bg * 4 + bb;
        __syncthreads();
        for (int i = tid; i < 2048; i += 256) {
            int ky = i & 31, ic = i >> 5;
            float2 v = *(const float2*)&xf[((size_t)(b*64 + ic))*4096 + kxi*64 + 2*ky];
            packsplit(v.x, v.y, sAh[ky*68 + ic], sAl[ky*68 + ic]);
        }
        __syncthreads();
        float c[4][4];
#pragma unroll
        for (int i = 0; i < 4; i++) { c[i][0]=c[i][1]=c[i][2]=c[i][3]=0.f; }
#pragma unroll
        for (int ks = 0; ks < 8; ks++) {
            int r = mt*16 + g, k0 = ks*8 + tg;
            unsigned ah[4] = {sAh[r*68+k0], sAh[(r+8)*68+k0], sAh[r*68+k0+4], sAh[(r+8)*68+k0+4]};
            unsigned al[4] = {sAl[r*68+k0], sAl[(r+8)*68+k0], sAl[r*68+k0+4], sAl[(r+8)*68+k0+4]};
#pragma unroll
            for (int j = 0; j < 4; j++) {
                int n = (ng*4 + j)*8 + g;
                unsigned bh[2] = {sBh[n*68+k0], sBh[n*68+k0+4]};
                unsigned bl[2] = {sBl[n*68+k0], sBl[n*68+k0+4]};
                mma3b(c[j], ah, al, bh, bl);
            }
        }
#pragma unroll
        for (int j = 0; j < 4; j++) {
            int ch = (ng*4 + j)*4 + tg;
            int ky0 = mt*16 + g;
            g_T[(((size_t)b*64 + kxi)*32 + ky0)*64 + ch]     = make_float2(c[j][0], c[j][1]);
            g_T[(((size_t)b*64 + kxi)*32 + ky0 + 8)*64 + ch] = make_float2(c[j][2], c[j][3]);
        }
    }
}

// ---- K3b (MMA): per (ky, 2b): OF[kxi][o] = T @ WY, M=64 N=128 K=128 ----
#define K3B_SMEM ((2*64*68 + 2*128*68) * 4)
__global__ void __launch_bounds__(256) k3b_mma() {
    extern __shared__ unsigned sm[];
    unsigned* sAh = sm;
    unsigned* sAl = sAh + 64*68;
    unsigned* sBh = sAl + 64*68;
    unsigned* sBl = sBh + 128*68;
    const int tid = threadIdx.x, warp = tid >> 5, lane = tid & 31;
    const int g = lane >> 2, tg = lane & 3;
    const int ky = blockIdx.x, bg = blockIdx.y;
    const int mt = warp >> 1, ng = warp & 1;

    for (int i = tid; i < 8192; i += 256) {
        int n = i >> 6, k2 = i & 63;
        sBh[n*68 + k2] = g_WYh[((size_t)ky*128 + n)*64 + k2];
        sBl[n*68 + k2] = g_WYl[((size_t)ky*128 + n)*64 + k2];
    }
    for (int bb = 0; bb < 2; bb++) {
        int b = bg * 2 + bb;
        __syncthreads();
        for (int i = tid; i < 4096; i += 256) {
            int c2 = i & 63, kxi = i >> 6;
            float2 v = g_T[(((size_t)b*64 + kxi)*32 + ky)*64 + c2];
            packsplit(v.x, v.y, sAh[kxi*68 + c2], sAl[kxi*68 + c2]);
        }
        __syncthreads();
        float c[8][4];
#pragma unroll
        for (int i = 0; i < 8; i++) { c[i][0]=c[i][1]=c[i][2]=c[i][3]=0.f; }
#pragma unroll
        for (int ks = 0; ks < 8; ks++) {
            int r = mt*16 + g, k0 = ks*8 + tg;
            unsigned ah[4] = {sAh[r*68+k0], sAh[(r+8)*68+k0], sAh[r*68+k0+4], sAh[(r+8)*68+k0+4]};
            unsigned al[4] = {sAl[r*68+k0], sAl[(r+8)*68+k0], sAl[r*68+k0+4], sAl[(r+8)*68+k0+4]};
#pragma unroll
            for (int j = 0; j < 8; j++) {
                int n = (ng*8 + j)*8 + g;
                unsigned bh[2] = {sBh[n*68+k0], sBh[n*68+k0+4]};
                unsigned bl[2] = {sBl[n*68+k0], sBl[n*68+k0+4]};
                mma3b(c[j], ah, al, bh, bl);
            }
        }
#pragma unroll
        for (int j = 0; j < 8; j++) {
            int o = (ng*8 + j)*4 + tg;
            int kxi0 = mt*16 + g;
            unsigned h, l;
            packsplit(c[j][0], c[j][1], h, l);
            g_OFh[(((size_t)b*64 + o)*64 + kxi0)*32 + ky] = h;
            g_OFl[(((size_t)b*64 + o)*64 + kxi0)*32 + ky] = l;
            packsplit(c[j][2], c[j][3], h, l);
            g_OFh[(((size_t)b*64 + o)*64 + kxi0 + 8)*32 + ky] = h;
            g_OFl[(((size_t)b*64 + o)*64 + kxi0 + 8)*32 + ky] = l;
        }
    }
}

// ---- S5: Z = A5 @ OutF (unchanged R12) ----
__global__ void __launch_bounds__(256) s5_invh() {
    __shared__ unsigned sAh[256][9], sAl[256][9], sFh[64][33], sFl[64][33];
    const int tid = threadIdx.x, warp = tid >> 5, lane = tid & 31;
    const int g = lane >> 2, tg = lane & 3;
    const int mh = blockIdx.x, bo = blockIdx.y;
    for (int i = tid; i < 2048; i += 256) {
        int kxi = i >> 5, ky = i & 31;
        sFh[kxi][ky] = g_OFh[(size_t)bo * 2048 + i];
        sFl[kxi][ky] = g_OFl[(size_t)bo * 2048 + i];
    }
    float c[2][4][4];
#pragma unroll
    for (int a = 0; a < 2; a++)
#pragma unroll
        for (int i = 0; i < 4; i++) { c[a][i][0]=c[a][i][1]=c[a][i][2]=c[a][i][3]=0.f; }
    for (int kc = 0; kc < 8; kc++) {
        __syncthreads();
        for (int i = tid; i < 2048; i += 256) {
            int row = i >> 3, col = i & 7;
            sAh[row][col] = g_A5ph[(mh * 256 + row) * 64 + kc * 8 + col];
            sAl[row][col] = g_A5pl[(mh * 256 + row) * 64 + kc * 8 + col];
        }
        __syncthreads();
        unsigned bha[4][2], bla[4][2];
#pragma unroll
        for (int nt = 0; nt < 4; nt++) {
            int n = nt * 8 + g;
            bha[nt][0] = sFh[kc*8+tg][n]; bha[nt][1] = sFh[kc*8+tg+4][n];
            bla[nt][0] = sFl[kc*8+tg][n]; bla[nt][1] = sFl[kc*8+tg+4][n];
        }
#pragma unroll
        for (int mt = 0; mt < 2; mt++) {
            int r = warp * 32 + mt * 16 + g;
            unsigned ah[4] = {sAh[r][tg], sAh[r+8][tg], sAh[r][tg+4], sAh[r+8][tg+4]};
            unsigned al[4] = {sAl[r][tg], sAl[r+8][tg], sAl[r][tg+4], sAl[r+8][tg+4]};
#pragma unroll
            for (int nt = 0; nt < 4; nt++)
                mma3b(c[mt][nt], ah, al, bha[nt], bla[nt]);
        }
    }
    float* z = g_Z + (size_t)bo * 16384;
#pragma unroll
    for (int mt = 0; mt < 2; mt++)
#pragma unroll
        for (int nt = 0; nt < 4; nt++) {
            int m0 = mh * 256 + warp * 32 + mt * 16 + g, m1 = m0 + 8;
            int n0 = nt * 8 + 2 * tg, n1 = n0 + 1;
            z[(m0 >> 1) * 64 + 2 * n0 + (m0 & 1)] = c[mt][nt][0];
            z[(m0 >> 1) * 64 + 2 * n1 + (m0 & 1)] = c[mt][nt][1];
            z[(m1 >> 1) * 64 + 2 * n0 + (m1 & 1)] = c[mt][nt][2];
            z[(m1 >> 1) * 64 + 2 * n1 + (m1 & 1)] = c[mt][nt][3];
        }
}

// ---- S6: out = Z @ C6 (unchanged R12) ----
__global__ void __launch_bounds__(256) s6_invw(float* __restrict__ out) {
    __shared__ unsigned sZh[128][17], sZl[128][17], sCh[128][17], sCl[128][17];
    const int tid = threadIdx.x, warp = tid >> 5, lane = tid & 31;
    const int g = lane >> 2, tg = lane & 3;
    const int mt2 = blockIdx.x, nt2 = blockIdx.y, bo = blockIdx.z;
    float c[16][4];
#pragma unroll
    for (int i = 0; i < 16; i++) { c[i][0]=c[i][1]=c[i][2]=c[i][3]=0.f; }
    const float* z = g_Z + (size_t)bo * 16384;
    for (int kc = 0; kc < 2; kc++) {
        __syncthreads();
        for (int i = tid; i < 2048; i += 256) {
            int row = i >> 4, col = i & 15;
            float2 zv = *(const float2*)&z[(mt2 * 128 + row) * 64 + kc * 32 + 2 * col];
            packsplit(zv.x, zv.y, sZh[row][col], sZl[row][col]);
        }
        for (int i = tid; i < 2048; i += 256) {
            int nl = i >> 4, col = i & 15;
            sCh[nl][col] = g_C6ph[(nt2 * 128 + nl) * 32 + kc * 16 + col];
            sCl[nl][col] = g_C6pl[(nt2 * 128 + nl) * 32 + kc * 16 + col];
        }
        __syncthreads();
#pragma unroll
        for (int ks = 0; ks < 2; ks++) {
            int r = warp * 16 + g, k0 = ks * 8 + tg;
            unsigned ah[4] = {sZh[r][k0], sZh[r+8][k0], sZh[r][k0+4], sZh[r+8][k0+4]};
            unsigned al[4] = {sZl[r][k0], sZl[r+8][k0], sZl[r][k0+4], sZl[r+8][k0+4]};
#pragma unroll
            for (int nt = 0; nt < 16; nt++) {
                int n = nt * 8 + g;
                unsigned bh[2] = {sCh[n][k0], sCh[n][k0+4]};
                unsigned bl[2] = {sCl[n][k0], sCl[n][k0+4]};
                mma3b(c[nt], ah, al, bh, bl);
            }
        }
    }
    float* orow = out + (size_t)bo * 65536;
#pragma unroll
    for (int nt = 0; nt < 16; nt++) {
        int h = mt2 * 128 + warp * 16 + g;
        int w = nt2 * 128 + nt * 8 + 2 * tg;
        *(float2*)&orow[(h)     * 256 + w] = make_float2(c[nt][0], c[nt][1]);
        *(float2*)&orow[(h + 8) * 256 + w] = make_float2(c[nt][2], c[nt][3]);
    }
}

extern "C" void kernel_launch(void* const* d_in, const int* in_sizes, int n_in,
                              void* d_out, int out_size) {
    const float* x   = (const float*)d_in[0];
    const float* wx1 = (const float*)d_in[1];
    const float* wx2 = (const float*)d_in[2];
    const float* wy  = (const float*)d_in[3];
    float* out = (float*)d_out;

    cudaFuncSetAttribute(k3a_mma, cudaFuncAttributeMaxDynamicSharedMemorySize, K3A_SMEM);
    cudaFuncSetAttribute(k3b_mma, cudaFuncAttributeMaxDynamicSharedMemorySize, K3B_SMEM);

    fill_all<<<128, 256>>>();
    fill_w<<<3072, 256>>>(wx1, wx2, wy);
    s1_wdft<<<2048, 256>>>(x);
    s2_hdft<<<1024, 256>>>();
    k3a_mma<<<dim3(64, 4), 256, K3A_SMEM>>>();
    k3b_mma<<<dim3(32, 8), 256, K3B_SMEM>>>();
    s5_invh<<<dim3(2, 1024), 256>>>();
    s6_invw<<<dim3(2, 2, 1024), 256>>>(out);
}

// round 15
// speedup vs baseline: 1.8942x; 1.0282x over previous
#include <cuda_runtime.h>
#include <cuda_bf16.h>
#include <math.h>
#include <stdint.h>

#define BB 16
#define CN 64

// ---- scratch (hi/lo interleaved as uint2) ----
__device__ uint2  g_Y1p[BB*CN*256*32];
__device__ float2 g_Xf [BB*CN*64*32];
__device__ float2 g_T  [BB*CN*64*32];            // [b][kxi][ky][c]
__device__ uint2  g_OFp[BB*CN*64*32];
__device__ float  g_Z  [BB*CN*256*64];
// stationary packed planes
__device__ uint2 g_B1p[64*128];
__device__ uint2 g_A2p[128*256];
__device__ uint2 g_A5p[512*64];
__device__ uint2 g_C6p[256*32];
__device__ uint2 g_WXp[64*128*64];
__device__ uint2 g_WYp[32*128*64];

__device__ __forceinline__ uint2 packsplit(float a, float b) {
    __nv_bfloat162 hv = __floats2bfloat162_rn(a, b);
    __nv_bfloat162 lv = __floats2bfloat162_rn(a - __bfloat162float(hv.x),
                                              b - __bfloat162float(hv.y));
    return make_uint2(*(unsigned*)&hv, *(unsigned*)&lv);
}
__device__ __forceinline__ void mmab(float* c, const unsigned* a, const unsigned* b) {
    asm volatile(
        "mma.sync.aligned.m16n8k16.row.col.f32.bf16.bf16.f32 "
        "{%0,%1,%2,%3},{%4,%5,%6,%7},{%8,%9},{%0,%1,%2,%3};"
        : "+f"(c[0]), "+f"(c[1]), "+f"(c[2]), "+f"(c[3])
        : "r"(a[0]), "r"(a[1]), "r"(a[2]), "r"(a[3]), "r"(b[0]), "r"(b[1]));
}
// 3-term: hh + lh + hl, operands arrive as uint2 (x=hi, y=lo)
__device__ __forceinline__ void mma3v(float* c, const uint2* a, const uint2* b) {
    unsigned ah[4] = {a[0].x, a[1].x, a[2].x, a[3].x};
    unsigned al[4] = {a[0].y, a[1].y, a[2].y, a[3].y};
    unsigned bh[2] = {b[0].x, b[1].x};
    unsigned bl[2] = {b[0].y, b[1].y};
    mmab(c, ah, bh); mmab(c, al, bh); mmab(c, ah, bl);
}

// ---- fills ----
__global__ void __launch_bounds__(256) fill_all() {
    int idx = blockIdx.x * 256 + threadIdx.x;   // 32768
    {   int m = idx >> 8, k2 = idx & 255;
        int kxi = m >> 1, t = m & 1, kx = (kxi < 32) ? kxi : 192 + kxi;
        float s, c; sincospif((float)((kx * k2) & 255) / 128.0f, &s, &c);
        g_A2p[idx] = packsplit((t ? -s : c) * (1.0f/16.0f), (t ? c : s) * (1.0f/16.0f));
    }
    {   int m = idx >> 6, k2 = idx & 63;
        int h = m >> 1, t = m & 1, kx = (k2 < 32) ? k2 : 192 + k2;
        float s, c; sincospif((float)((kx * h) & 255) / 128.0f, &s, &c);
        g_A5p[idx] = packsplit((t ? s : c), (t ? c : -s));
    }
    if (idx < 8192) {
        int n = idx >> 7, k2 = idx & 127;
        int ky = n >> 1, t = n & 1;
        float s0, c0, s1, c1;
        sincospif((float)(((2*k2) * ky) & 255) / 128.0f, &s0, &c0);
        sincospif((float)(((2*k2+1) * ky) & 255) / 128.0f, &s1, &c1);
        g_B1p[idx] = packsplit((t ? -s0 : c0) * (1.0f/16.0f), (t ? -s1 : c1) * (1.0f/16.0f));
    }
    if (idx < 8192) {
        int w = idx >> 5, ky = idx & 31;
        float s, c; sincospif((float)((ky * w) & 255) / 128.0f, &s, &c);
        float base = ((ky == 0) ? 1.0f : 2.0f) * (1.0f/256.0f);
        g_C6p[idx] = packsplit(base * c, (ky == 0) ? 0.0f : -base * s);
    }
}
__global__ void __launch_bounds__(256) fill_w(const float* __restrict__ wx1,
                                              const float* __restrict__ wx2,
                                              const float* __restrict__ wy) {
    int idx = blockIdx.x * 256 + threadIdx.x;   // 786432
    if (idx < 524288) {
        int k2 = idx & 63, n = (idx >> 6) & 127, m = idx >> 13;
        const float2* src = (const float2*)((m < 32) ? wx1 : wx2);
        float2 w = src[(k2 * 64 + (n >> 1)) * 32 + (m & 31)];
        g_WXp[idx] = packsplit((n & 1) ? w.y : w.x, (n & 1) ? w.x : -w.y);
    } else {
        int r = idx - 524288;
        int k2 = r & 63, n = (r >> 6) & 127;
        float2 w = ((const float2*)wy)[(k2 * 64 + (n >> 1)) * 32 + (r >> 13)];
        g_WYp[r] = packsplit((n & 1) ? w.y : w.x, (n & 1) ? w.x : -w.y);
    }
}

// ---- S1: Y1 = x @ B1 (M=128/CTA, K=256, N=64) ----
__global__ void __launch_bounds__(256) s1_wdft(const float* __restrict__ x) {
    __shared__ uint2 sX[128][17], sB[64][17];
    const int tid = threadIdx.x, warp = tid >> 5, lane = tid & 31;
    const int g = lane >> 2, tg = lane & 3;
    const size_t r0 = (size_t)blockIdx.x * 128;
    float c[8][4];
#pragma unroll
    for (int i = 0; i < 8; i++) { c[i][0]=c[i][1]=c[i][2]=c[i][3]=0.f; }
    for (int kc = 0; kc < 8; kc++) {
        __syncthreads();
        for (int i = tid; i < 2048; i += 256) {
            int row = i >> 4, col = i & 15;
            float2 v = *(const float2*)&x[(r0 + row) * 256 + kc * 32 + 2 * col];
            sX[row][col] = packsplit(v.x, v.y);
        }
        for (int i = tid; i < 1024; i += 256) {
            int n = i >> 4, col = i & 15;
            sB[n][col] = g_B1p[n * 128 + kc * 16 + col];
        }
        __syncthreads();
#pragma unroll
        for (int ks = 0; ks < 2; ks++) {
            int r = warp * 16 + g, k0 = ks * 8 + tg;
            uint2 a[4] = {sX[r][k0], sX[r+8][k0], sX[r][k0+4], sX[r+8][k0+4]};
#pragma unroll
            for (int nt = 0; nt < 8; nt++) {
                int n = nt * 8 + g;
                uint2 b[2] = {sB[n][k0], sB[n][k0+4]};
                mma3v(c[nt], a, b);
            }
        }
    }
#pragma unroll
    for (int nt = 0; nt < 8; nt++) {
        size_t m = r0 + warp * 16 + g;
        int ky = nt * 4 + tg;
        g_Y1p[m * 32 + ky]       = packsplit(c[nt][0], c[nt][1]);
        g_Y1p[(m + 8) * 32 + ky] = packsplit(c[nt][2], c[nt][3]);
    }
}

// ---- S2: Xf = A2 @ Y1slab (M=128, K=512, N=32) ----
__global__ void __launch_bounds__(256) s2_hdft() {
    __shared__ uint2 sA[128][17], sY[16][33];
    const int tid = threadIdx.x, warp = tid >> 5, lane = tid & 31;
    const int g = lane >> 2, tg = lane & 3;
    const int bi = blockIdx.x;
    float c[4][4];
#pragma unroll
    for (int i = 0; i < 4; i++) { c[i][0]=c[i][1]=c[i][2]=c[i][3]=0.f; }
    for (int kc = 0; kc < 16; kc++) {
        __syncthreads();
        for (int i = tid; i < 2048; i += 256) {
            int row = i >> 4, col = i & 15;
            sA[row][col] = g_A2p[row * 256 + kc * 16 + col];
        }
        for (int i = tid; i < 512; i += 256) {
            int hl = i >> 5, ky = i & 31;
            sY[hl][ky] = g_Y1p[((size_t)bi * 256 + kc * 16 + hl) * 32 + ky];
        }
        __syncthreads();
#pragma unroll
        for (int ks = 0; ks < 2; ks++) {
            int r = warp * 16 + g, k0 = ks * 8 + tg;
            uint2 a[4] = {sA[r][k0], sA[r+8][k0], sA[r][k0+4], sA[r+8][k0+4]};
#pragma unroll
            for (int nt = 0; nt < 4; nt++) {
                int n = nt * 8 + g;
                uint2 b[2] = {sY[k0][n], sY[k0+4][n]};
                mma3v(c[nt], a, b);
            }
        }
    }
    float* xf = (float*)g_Xf + (size_t)bi * 4096;
#pragma unroll
    for (int nt = 0; nt < 4; nt++) {
        int m0 = warp * 16 + g, m1 = m0 + 8;
        int n0 = nt * 8 + 2 * tg, n1 = n0 + 1;
        xf[(m0 >> 1) * 64 + 2 * n0 + (m0 & 1)] = c[nt][0];
        xf[(m0 >> 1) * 64 + 2 * n1 + (m0 & 1)] = c[nt][1];
        xf[(m1 >> 1) * 64 + 2 * n0 + (m1 & 1)] = c[nt][2];
        xf[(m1 >> 1) * 64 + 2 * n1 + (m1 & 1)] = c[nt][3];
    }
}

// ---- K3a (MMA): per (kxi, 4b): T = X @ WX, M=32 N=128 K=128 ----
#define K3A_SMEM ((32*65 + 128*65) * 8)
__global__ void __launch_bounds__(256) k3a_mma() {
    extern __shared__ uint2 sm[];
    uint2* sA = sm;                 // [32][65]
    uint2* sB = sA + 32*65;         // [128][65]
    const int tid = threadIdx.x, warp = tid >> 5, lane = tid & 31;
    const int g = lane >> 2, tg = lane & 3;
    const int kxi = blockIdx.x, bg = blockIdx.y;
    const int mt = warp >> 2, ng = warp & 3;

    for (int i = tid; i < 8192; i += 256) {
        int n = i >> 6, k2 = i & 63;
        sB[n*65 + k2] = g_WXp[((size_t)kxi*128 + n)*64 + k2];
    }
    const float* xf = (const float*)g_Xf;
    for (int bb = 0; bb < 4; bb++) {
        int b = bg * 4 + bb;
        __syncthreads();
        for (int i = tid; i < 2048; i += 256) {
            int ky = i & 31, ic = i >> 5;
            float2 v = *(const float2*)&xf[((size_t)(b*64 + ic))*4096 + kxi*64 + 2*ky];
            sA[ky*65 + ic] = packsplit(v.x, v.y);
        }
        __syncthreads();
        float c[4][4];
#pragma unroll
        for (int i = 0; i < 4; i++) { c[i][0]=c[i][1]=c[i][2]=c[i][3]=0.f; }
#pragma unroll
        for (int ks = 0; ks < 8; ks++) {
            int r = mt*16 + g, k0 = ks*8 + tg;
            uint2 a[4] = {sA[r*65+k0], sA[(r+8)*65+k0], sA[r*65+k0+4], sA[(r+8)*65+k0+4]};
#pragma unroll
            for (int j = 0; j < 4; j++) {
                int n = (ng*4 + j)*8 + g;
                uint2 bfr[2] = {sB[n*65+k0], sB[n*65+k0+4]};
                mma3v(c[j], a, bfr);
            }
        }
#pragma unroll
        for (int j = 0; j < 4; j++) {
            int ch = (ng*4 + j)*4 + tg;
            int ky0 = mt*16 + g;
            g_T[(((size_t)b*64 + kxi)*32 + ky0)*64 + ch]     = make_float2(c[j][0], c[j][1]);
            g_T[(((size_t)b*64 + kxi)*32 + ky0 + 8)*64 + ch] = make_float2(c[j][2], c[j][3]);
        }
    }
}

// ---- K3b (MMA): per (ky, 2b): OF = T @ WY, M=64 N=128 K=128 ----
#define K3B_SMEM ((64*65 + 128*65) * 8)
__global__ void __launch_bounds__(256) k3b_mma() {
    extern __shared__ uint2 sm[];
    uint2* sA = sm;                 // [64][65]
    uint2* sB = sA + 64*65;         // [128][65]
    const int tid = threadIdx.x, warp = tid >> 5, lane = tid & 31;
    const int g = lane >> 2, tg = lane & 3;
    const int ky = blockIdx.x, bg = blockIdx.y;
    const int mt = warp >> 1, ng = warp & 1;

    for (int i = tid; i < 8192; i += 256) {
        int n = i >> 6, k2 = i & 63;
        sB[n*65 + k2] = g_WYp[((size_t)ky*128 + n)*64 + k2];
    }
    for (int bb = 0; bb < 2; bb++) {
        int b = bg * 2 + bb;
        __syncthreads();
        for (int i = tid; i < 4096; i += 256) {
            int c2 = i & 63, kxi = i >> 6;
            float2 v = g_T[(((size_t)b*64 + kxi)*32 + ky)*64 + c2];
            sA[kxi*65 + c2] = packsplit(v.x, v.y);
        }
        __syncthreads();
        float c[8][4];
#pragma unroll
        for (int i = 0; i < 8; i++) { c[i][0]=c[i][1]=c[i][2]=c[i][3]=0.f; }
#pragma unroll
        for (int ks = 0; ks < 8; ks++) {
            int r = mt*16 + g, k0 = ks*8 + tg;
            uint2 a[4] = {sA[r*65+k0], sA[(r+8)*65+k0], sA[r*65+k0+4], sA[(r+8)*65+k0+4]};
#pragma unroll
            for (int j = 0; j < 8; j++) {
                int n = (ng*8 + j)*8 + g;
                uint2 bfr[2] = {sB[n*65+k0], sB[n*65+k0+4]};
                mma3v(c[j], a, bfr);
            }
        }
#pragma unroll
        for (int j = 0; j < 8; j++) {
            int o = (ng*8 + j)*4 + tg;
            int kxi0 = mt*16 + g;
            g_OFp[(((size_t)b*64 + o)*64 + kxi0)*32 + ky]     = packsplit(c[j][0], c[j][1]);
            g_OFp[(((size_t)b*64 + o)*64 + kxi0 + 8)*32 + ky] = packsplit(c[j][2], c[j][3]);
        }
    }
}

// ---- S5: Z = A5 @ OutF (M=512, K=128, N=32) ----
__global__ void __launch_bounds__(256) s5_invh() {
    __shared__ uint2 sA[256][9], sF[64][33];
    const int tid = threadIdx.x, warp = tid >> 5, lane = tid & 31;
    const int g = lane >> 2, tg = lane & 3;
    const int mh = blockIdx.x, bo = blockIdx.y;
    for (int i = tid; i < 2048; i += 256) {
        int kxi = i >> 5, ky = i & 31;
        sF[kxi][ky] = g_OFp[(size_t)bo * 2048 + i];
    }
    float c[2][4][4];
#pragma unroll
    for (int a = 0; a < 2; a++)
#pragma unroll
        for (int i = 0; i < 4; i++) { c[a][i][0]=c[a][i][1]=c[a][i][2]=c[a][i][3]=0.f; }
    for (int kc = 0; kc < 8; kc++) {
        __syncthreads();
        for (int i = tid; i < 2048; i += 256) {
            int row = i >> 3, col = i & 7;
            sA[row][col] = g_A5p[(mh * 256 + row) * 64 + kc * 8 + col];
        }
        __syncthreads();
        uint2 bfr[4][2];
#pragma unroll
        for (int nt = 0; nt < 4; nt++) {
            int n = nt * 8 + g;
            bfr[nt][0] = sF[kc*8+tg][n];
            bfr[nt][1] = sF[kc*8+tg+4][n];
        }
#pragma unroll
        for (int mt = 0; mt < 2; mt++) {
            int r = warp * 32 + mt * 16 + g;
            uint2 a[4] = {sA[r][tg], sA[r+8][tg], sA[r][tg+4], sA[r+8][tg+4]};
#pragma unroll
            for (int nt = 0; nt < 4; nt++)
                mma3v(c[mt][nt], a, bfr[nt]);
        }
    }
    float* z = g_Z + (size_t)bo * 16384;
#pragma unroll
    for (int mt = 0; mt < 2; mt++)
#pragma unroll
        for (int nt = 0; nt < 4; nt++) {
            int m0 = mh * 256 + warp * 32 + mt * 16 + g, m1 = m0 + 8;
            int n0 = nt * 8 + 2 * tg, n1 = n0 + 1;
            z[(m0 >> 1) * 64 + 2 * n0 + (m0 & 1)] = c[mt][nt][0];
            z[(m0 >> 1) * 64 + 2 * n1 + (m0 & 1)] = c[mt][nt][1];
            z[(m1 >> 1) * 64 + 2 * n0 + (m1 & 1)] = c[mt][nt][2];
            z[(m1 >> 1) * 64 + 2 * n1 + (m1 & 1)] = c[mt][nt][3];
        }
}

// ---- S6: out = Z @ C6 (M=256, K=64, N=256) ----
__global__ void __launch_bounds__(256) s6_invw(float* __restrict__ out) {
    __shared__ uint2 sZ[128][17], sC[128][17];
    const int tid = threadIdx.x, warp = tid >> 5, lane = tid & 31;
    const int g = lane >> 2, tg = lane & 3;
    const int mt2 = blockIdx.x, nt2 = blockIdx.y, bo = blockIdx.z;
    float c[16][4];
#pragma unroll
    for (int i = 0; i < 16; i++) { c[i][0]=c[i][1]=c[i][2]=c[i][3]=0.f; }
    const float* z = g_Z + (size_t)bo * 16384;
    for (int kc = 0; kc < 2; kc++) {
        __syncthreads();
        for (int i = tid; i < 2048; i += 256) {
            int row = i >> 4, col = i & 15;
            float2 zv = *(const float2*)&z[(mt2 * 128 + row) * 64 + kc * 32 + 2 * col];
            sZ[row][col] = packsplit(zv.x, zv.y);
        }
        for (int i = tid; i < 2048; i += 256) {
            int nl = i >> 4, col = i & 15;
            sC[nl][col] = g_C6p[(nt2 * 128 + nl) * 32 + kc * 16 + col];
        }
        __syncthreads();
#pragma unroll
        for (int ks = 0; ks < 2; ks++) {
            int r = warp * 16 + g, k0 = ks * 8 + tg;
            uint2 a[4] = {sZ[r][k0], sZ[r+8][k0], sZ[r][k0+4], sZ[r+8][k0+4]};
#pragma unroll
            for (int nt = 0; nt < 16; nt++) {
                int n = nt * 8 + g;
                uint2 bfr[2] = {sC[n][k0], sC[n][k0+4]};
                mma3v(c[nt], a, bfr);
            }
        }
    }
    float* orow = out + (size_t)bo * 65536;
#pragma unroll
    for (int nt = 0; nt < 16; nt++) {
        int h = mt2 * 128 + warp * 16 + g;
        int w = nt2 * 128 + nt * 8 + 2 * tg;
        *(float2*)&orow[(h)     * 256 + w] = make_float2(c[nt][0], c[nt][1]);
        *(float2*)&orow[(h + 8) * 256 + w] = make_float2(c[nt][2], c[nt][3]);
    }
}

extern "C" void kernel_launch(void* const* d_in, const int* in_sizes, int n_in,
                              void* d_out, int out_size) {
    const float* x   = (const float*)d_in[0];
    const float* wx1 = (const float*)d_in[1];
    const float* wx2 = (const float*)d_in[2];
    const float* wy  = (const float*)d_in[3];
    float* out = (float*)d_out;

    cudaFuncSetAttribute(k3a_mma, cudaFuncAttributeMaxDynamicSharedMemorySize, K3A_SMEM);
    cudaFuncSetAttribute(k3b_mma, cudaFuncAttributeMaxDynamicSharedMemorySize, K3B_SMEM);

    fill_all<<<128, 256>>>();
    fill_w<<<3072, 256>>>(wx1, wx2, wy);
    s1_wdft<<<2048, 256>>>(x);
    s2_hdft<<<1024, 256>>>();
    k3a_mma<<<dim3(64, 4), 256, K3A_SMEM>>>();
    k3b_mma<<<dim3(32, 8), 256, K3B_SMEM>>>();
    s5_invh<<<dim3(2, 1024), 256>>>();
    s6_invw<<<dim3(2, 2, 1024), 256>>>(out);
}

// round 16
// speedup vs baseline: 1.9710x; 1.0405x over previous
#include <cuda_runtime.h>
#include <cuda_bf16.h>
#include <math.h>
#include <stdint.h>

#define BB 16
#define CN 64

// ---- scratch (hi/lo interleaved as uint2) ----
__device__ uint2  g_Y1p[BB*CN*256*32];
__device__ float2 g_Xf [BB*CN*64*32];
__device__ float2 g_T  [BB*CN*64*32];            // [b][kxi][ky][c]
__device__ uint2  g_OFp[BB*CN*64*32];
__device__ float  g_Z  [BB*CN*256*64];
// stationary packed planes
__device__ uint2 g_B1p[64*128];
__device__ uint2 g_A2p[128*256];
__device__ uint2 g_A5p[512*64];
__device__ uint2 g_C6p[256*32];
__device__ uint2 g_WXp[64*128*64];
__device__ uint2 g_WYp[32*128*64];

__device__ __forceinline__ uint2 packsplit(float a, float b) {
    __nv_bfloat162 hv = __floats2bfloat162_rn(a, b);
    __nv_bfloat162 lv = __floats2bfloat162_rn(a - __bfloat162float(hv.x),
                                              b - __bfloat162float(hv.y));
    return make_uint2(*(unsigned*)&hv, *(unsigned*)&lv);
}
__device__ __forceinline__ void mmab(float* c, const unsigned* a, const unsigned* b) {
    asm volatile(
        "mma.sync.aligned.m16n8k16.row.col.f32.bf16.bf16.f32 "
        "{%0,%1,%2,%3},{%4,%5,%6,%7},{%8,%9},{%0,%1,%2,%3};"
        : "+f"(c[0]), "+f"(c[1]), "+f"(c[2]), "+f"(c[3])
        : "r"(a[0]), "r"(a[1]), "r"(a[2]), "r"(a[3]), "r"(b[0]), "r"(b[1]));
}
__device__ __forceinline__ void mma3v(float* c, const uint2* a, const uint2* b) {
    unsigned ah[4] = {a[0].x, a[1].x, a[2].x, a[3].x};
    unsigned al[4] = {a[0].y, a[1].y, a[2].y, a[3].y};
    unsigned bh[2] = {b[0].x, b[1].x};
    unsigned bl[2] = {b[0].y, b[1].y};
    mmab(c, ah, bh); mmab(c, al, bh); mmab(c, ah, bl);
}

// ---- fills ----
__global__ void __launch_bounds__(256) fill_all() {
    int idx = blockIdx.x * 256 + threadIdx.x;   // 32768
    {   int m = idx >> 8, k2 = idx & 255;
        int kxi = m >> 1, t = m & 1, kx = (kxi < 32) ? kxi : 192 + kxi;
        float s, c; sincospif((float)((kx * k2) & 255) / 128.0f, &s, &c);
        g_A2p[idx] = packsplit((t ? -s : c) * (1.0f/16.0f), (t ? c : s) * (1.0f/16.0f));
    }
    {   int m = idx >> 6, k2 = idx & 63;
        int h = m >> 1, t = m & 1, kx = (k2 < 32) ? k2 : 192 + k2;
        float s, c; sincospif((float)((kx * h) & 255) / 128.0f, &s, &c);
        g_A5p[idx] = packsplit((t ? s : c), (t ? c : -s));
    }
    if (idx < 8192) {
        int n = idx >> 7, k2 = idx & 127;
        int ky = n >> 1, t = n & 1;
        float s0, c0, s1, c1;
        sincospif((float)(((2*k2) * ky) & 255) / 128.0f, &s0, &c0);
        sincospif((float)(((2*k2+1) * ky) & 255) / 128.0f, &s1, &c1);
        g_B1p[idx] = packsplit((t ? -s0 : c0) * (1.0f/16.0f), (t ? -s1 : c1) * (1.0f/16.0f));
    }
    if (idx < 8192) {
        int w = idx >> 5, ky = idx & 31;
        float s, c; sincospif((float)((ky * w) & 255) / 128.0f, &s, &c);
        float base = ((ky == 0) ? 1.0f : 2.0f) * (1.0f/256.0f);
        g_C6p[idx] = packsplit(base * c, (ky == 0) ? 0.0f : -base * s);
    }
}
__global__ void __launch_bounds__(256) fill_w(const float* __restrict__ wx1,
                                              const float* __restrict__ wx2,
                                              const float* __restrict__ wy) {
    int idx = blockIdx.x * 256 + threadIdx.x;   // 786432
    if (idx < 524288) {
        int k2 = idx & 63, n = (idx >> 6) & 127, m = idx >> 13;
        const float2* src = (const float2*)((m < 32) ? wx1 : wx2);
        float2 w = src[(k2 * 64 + (n >> 1)) * 32 + (m & 31)];
        g_WXp[idx] = packsplit((n & 1) ? w.y : w.x, (n & 1) ? w.x : -w.y);
    } else {
        int r = idx - 524288;
        int k2 = r & 63, n = (r >> 6) & 127;
        float2 w = ((const float2*)wy)[(k2 * 64 + (n >> 1)) * 32 + (r >> 13)];
        g_WYp[r] = packsplit((n & 1) ? w.y : w.x, (n & 1) ? w.x : -w.y);
    }
}

// ---- S1: Y1 = x @ B1 (unchanged R14) ----
__global__ void __launch_bounds__(256) s1_wdft(const float* __restrict__ x) {
    __shared__ uint2 sX[128][17], sB[64][17];
    const int tid = threadIdx.x, warp = tid >> 5, lane = tid & 31;
    const int g = lane >> 2, tg = lane & 3;
    const size_t r0 = (size_t)blockIdx.x * 128;
    float c[8][4];
#pragma unroll
    for (int i = 0; i < 8; i++) { c[i][0]=c[i][1]=c[i][2]=c[i][3]=0.f; }
    for (int kc = 0; kc < 8; kc++) {
        __syncthreads();
        for (int i = tid; i < 2048; i += 256) {
            int row = i >> 4, col = i & 15;
            float2 v = *(const float2*)&x[(r0 + row) * 256 + kc * 32 + 2 * col];
            sX[row][col] = packsplit(v.x, v.y);
        }
        for (int i = tid; i < 1024; i += 256) {
            int n = i >> 4, col = i & 15;
            sB[n][col] = g_B1p[n * 128 + kc * 16 + col];
        }
        __syncthreads();
#pragma unroll
        for (int ks = 0; ks < 2; ks++) {
            int r = warp * 16 + g, k0 = ks * 8 + tg;
            uint2 a[4] = {sX[r][k0], sX[r+8][k0], sX[r][k0+4], sX[r+8][k0+4]};
#pragma unroll
            for (int nt = 0; nt < 8; nt++) {
                int n = nt * 8 + g;
                uint2 b[2] = {sB[n][k0], sB[n][k0+4]};
                mma3v(c[nt], a, b);
            }
        }
    }
#pragma unroll
    for (int nt = 0; nt < 8; nt++) {
        size_t m = r0 + warp * 16 + g;
        int ky = nt * 4 + tg;
        g_Y1p[m * 32 + ky]       = packsplit(c[nt][0], c[nt][1]);
        g_Y1p[(m + 8) * 32 + ky] = packsplit(c[nt][2], c[nt][3]);
    }
}

// ---- S2 (batched x4): Xf[4 slabs] = A2 @ Y1, M=128, K=512, N=4x32 ----
__global__ void __launch_bounds__(256) s2_hdft() {
    __shared__ uint2 sA[128][17];         // 17.4KB
    __shared__ uint2 sY[4][16][33];       // 16.9KB
    const int tid = threadIdx.x, warp = tid >> 5, lane = tid & 31;
    const int g = lane >> 2, tg = lane & 3;
    const int bi0 = blockIdx.x * 4;
    float c[4][4][4];
#pragma unroll
    for (int s = 0; s < 4; s++)
#pragma unroll
        for (int i = 0; i < 4; i++) { c[s][i][0]=c[s][i][1]=c[s][i][2]=c[s][i][3]=0.f; }

    for (int kc = 0; kc < 16; kc++) {
        __syncthreads();
        for (int i = tid; i < 2048; i += 256) {
            int row = i >> 4, col = i & 15;
            sA[row][col] = g_A2p[row * 256 + kc * 16 + col];
        }
        for (int i = tid; i < 2048; i += 256) {
            int sl = i >> 9, rem = i & 511;
            int hl = rem >> 5, ky = rem & 31;
            sY[sl][hl][ky] = g_Y1p[((size_t)(bi0 + sl) * 256 + kc * 16 + hl) * 32 + ky];
        }
        __syncthreads();
#pragma unroll
        for (int ks = 0; ks < 2; ks++) {
            int r = warp * 16 + g, k0 = ks * 8 + tg;
            uint2 a[4] = {sA[r][k0], sA[r+8][k0], sA[r][k0+4], sA[r+8][k0+4]};
#pragma unroll
            for (int sl = 0; sl < 4; sl++)
#pragma unroll
                for (int nt = 0; nt < 4; nt++) {
                    int n = nt * 8 + g;
                    uint2 b[2] = {sY[sl][k0][n], sY[sl][k0+4][n]};
                    mma3v(c[sl][nt], a, b);
                }
        }
    }
#pragma unroll
    for (int sl = 0; sl < 4; sl++) {
        float* xf = (float*)g_Xf + (size_t)(bi0 + sl) * 4096;
#pragma unroll
        for (int nt = 0; nt < 4; nt++) {
            int m0 = warp * 16 + g, m1 = m0 + 8;
            int n0 = nt * 8 + 2 * tg, n1 = n0 + 1;
            xf[(m0 >> 1) * 64 + 2 * n0 + (m0 & 1)] = c[sl][nt][0];
            xf[(m0 >> 1) * 64 + 2 * n1 + (m0 & 1)] = c[sl][nt][1];
            xf[(m1 >> 1) * 64 + 2 * n0 + (m1 & 1)] = c[sl][nt][2];
            xf[(m1 >> 1) * 64 + 2 * n1 + (m1 & 1)] = c[sl][nt][3];
        }
    }
}

// ---- K3a (MMA, unchanged R14) ----
#define K3A_SMEM ((32*65 + 128*65) * 8)
__global__ void __launch_bounds__(256) k3a_mma() {
    extern __shared__ uint2 sm[];
    uint2* sA = sm;
    uint2* sB = sA + 32*65;
    const int tid = threadIdx.x, warp = tid >> 5, lane = tid & 31;
    const int g = lane >> 2, tg = lane & 3;
    const int kxi = blockIdx.x, bg = blockIdx.y;
    const int mt = warp >> 2, ng = warp & 3;

    for (int i = tid; i < 8192; i += 256) {
        int n = i >> 6, k2 = i & 63;
        sB[n*65 + k2] = g_WXp[((size_t)kxi*128 + n)*64 + k2];
    }
    const float* xf = (const float*)g_Xf;
    for (int bb = 0; bb < 4; bb++) {
        int b = bg * 4 + bb;
        __syncthreads();
        for (int i = tid; i < 2048; i += 256) {
            int ky = i & 31, ic = i >> 5;
            float2 v = *(const float2*)&xf[((size_t)(b*64 + ic))*4096 + kxi*64 + 2*ky];
            sA[ky*65 + ic] = packsplit(v.x, v.y);
        }
        __syncthreads();
        float c[4][4];
#pragma unroll
        for (int i = 0; i < 4; i++) { c[i][0]=c[i][1]=c[i][2]=c[i][3]=0.f; }
#pragma unroll
        for (int ks = 0; ks < 8; ks++) {
            int r = mt*16 + g, k0 = ks*8 + tg;
            uint2 a[4] = {sA[r*65+k0], sA[(r+8)*65+k0], sA[r*65+k0+4], sA[(r+8)*65+k0+4]};
#pragma unroll
            for (int j = 0; j < 4; j++) {
                int n = (ng*4 + j)*8 + g;
                uint2 bfr[2] = {sB[n*65+k0], sB[n*65+k0+4]};
                mma3v(c[j], a, bfr);
            }
        }
#pragma unroll
        for (int j = 0; j < 4; j++) {
            int ch = (ng*4 + j)*4 + tg;
            int ky0 = mt*16 + g;
            g_T[(((size_t)b*64 + kxi)*32 + ky0)*64 + ch]     = make_float2(c[j][0], c[j][1]);
            g_T[(((size_t)b*64 + kxi)*32 + ky0 + 8)*64 + ch] = make_float2(c[j][2], c[j][3]);
        }
    }
}

// ---- K3b (MMA, unchanged R14) ----
#define K3B_SMEM ((64*65 + 128*65) * 8)
__global__ void __launch_bounds__(256) k3b_mma() {
    extern __shared__ uint2 sm[];
    uint2* sA = sm;
    uint2* sB = sA + 64*65;
    const int tid = threadIdx.x, warp = tid >> 5, lane = tid & 31;
    const int g = lane >> 2, tg = lane & 3;
    const int ky = blockIdx.x, bg = blockIdx.y;
    const int mt = warp >> 1, ng = warp & 1;

    for (int i = tid; i < 8192; i += 256) {
        int n = i >> 6, k2 = i & 63;
        sB[n*65 + k2] = g_WYp[((size_t)ky*128 + n)*64 + k2];
    }
    for (int bb = 0; bb < 2; bb++) {
        int b = bg * 2 + bb;
        __syncthreads();
        for (int i = tid; i < 4096; i += 256) {
            int c2 = i & 63, kxi = i >> 6;
            float2 v = g_T[(((size_t)b*64 + kxi)*32 + ky)*64 + c2];
            sA[kxi*65 + c2] = packsplit(v.x, v.y);
        }
        __syncthreads();
        float c[8][4];
#pragma unroll
        for (int i = 0; i < 8; i++) { c[i][0]=c[i][1]=c[i][2]=c[i][3]=0.f; }
#pragma unroll
        for (int ks = 0; ks < 8; ks++) {
            int r = mt*16 + g, k0 = ks*8 + tg;
            uint2 a[4] = {sA[r*65+k0], sA[(r+8)*65+k0], sA[r*65+k0+4], sA[(r+8)*65+k0+4]};
#pragma unroll
            for (int j = 0; j < 8; j++) {
                int n = (ng*8 + j)*8 + g;
                uint2 bfr[2] = {sB[n*65+k0], sB[n*65+k0+4]};
                mma3v(c[j], a, bfr);
            }
        }
#pragma unroll
        for (int j = 0; j < 8; j++) {
            int o = (ng*8 + j)*4 + tg;
            int kxi0 = mt*16 + g;
            g_OFp[(((size_t)b*64 + o)*64 + kxi0)*32 + ky]     = packsplit(c[j][0], c[j][1]);
            g_OFp[(((size_t)b*64 + o)*64 + kxi0 + 8)*32 + ky] = packsplit(c[j][2], c[j][3]);
        }
    }
}

// ---- S5: Z = A5 @ OutF (unchanged R14) ----
__global__ void __launch_bounds__(256) s5_invh() {
    __shared__ uint2 sA[256][9], sF[64][33];
    const int tid = threadIdx.x, warp = tid >> 5, lane = tid & 31;
    const int g = lane >> 2, tg = lane & 3;
    const int mh = blockIdx.x, bo = blockIdx.y;
    for (int i = tid; i < 2048; i += 256) {
        int kxi = i >> 5, ky = i & 31;
        sF[kxi][ky] = g_OFp[(size_t)bo * 2048 + i];
    }
    float c[2][4][4];
#pragma unroll
    for (int a = 0; a < 2; a++)
#pragma unroll
        for (int i = 0; i < 4; i++) { c[a][i][0]=c[a][i][1]=c[a][i][2]=c[a][i][3]=0.f; }
    for (int kc = 0; kc < 8; kc++) {
        __syncthreads();
        for (int i = tid; i < 2048; i += 256) {
            int row = i >> 3, col = i & 7;
            sA[row][col] = g_A5p[(mh * 256 + row) * 64 + kc * 8 + col];
        }
        __syncthreads();
        uint2 bfr[4][2];
#pragma unroll
        for (int nt = 0; nt < 4; nt++) {
            int n = nt * 8 + g;
            bfr[nt][0] = sF[kc*8+tg][n];
            bfr[nt][1] = sF[kc*8+tg+4][n];
        }
#pragma unroll
        for (int mt = 0; mt < 2; mt++) {
            int r = warp * 32 + mt * 16 + g;
            uint2 a[4] = {sA[r][tg], sA[r+8][tg], sA[r][tg+4], sA[r+8][tg+4]};
#pragma unroll
            for (int nt = 0; nt < 4; nt++)
                mma3v(c[mt][nt], a, bfr[nt]);
        }
    }
    float* z = g_Z + (size_t)bo * 16384;
#pragma unroll
    for (int mt = 0; mt < 2; mt++)
#pragma unroll
        for (int nt = 0; nt < 4; nt++) {
            int m0 = mh * 256 + warp * 32 + mt * 16 + g, m1 = m0 + 8;
            int n0 = nt * 8 + 2 * tg, n1 = n0 + 1;
            z[(m0 >> 1) * 64 + 2 * n0 + (m0 & 1)] = c[mt][nt][0];
            z[(m0 >> 1) * 64 + 2 * n1 + (m0 & 1)] = c[mt][nt][1];
            z[(m1 >> 1) * 64 + 2 * n0 + (m1 & 1)] = c[mt][nt][2];
            z[(m1 >> 1) * 64 + 2 * n1 + (m1 & 1)] = c[mt][nt][3];
        }
}

// ---- S6: out = Z @ C6 (unchanged R14) ----
__global__ void __launch_bounds__(256) s6_invw(float* __restrict__ out) {
    __shared__ uint2 sZ[128][17], sC[128][17];
    const int tid = threadIdx.x, warp = tid >> 5, lane = tid & 31;
    const int g = lane >> 2, tg = lane & 3;
    const int mt2 = blockIdx.x, nt2 = blockIdx.y, bo = blockIdx.z;
    float c[16][4];
#pragma unroll
    for (int i = 0; i < 16; i++) { c[i][0]=c[i][1]=c[i][2]=c[i][3]=0.f; }
    const float* z = g_Z + (size_t)bo * 16384;
    for (int kc = 0; kc < 2; kc++) {
        __syncthreads();
        for (int i = tid; i < 2048; i += 256) {
            int row = i >> 4, col = i & 15;
            float2 zv = *(const float2*)&z[(mt2 * 128 + row) * 64 + kc * 32 + 2 * col];
            sZ[row][col] = packsplit(zv.x, zv.y);
        }
        for (int i = tid; i < 2048; i += 256) {
            int nl = i >> 4, col = i & 15;
            sC[nl][col] = g_C6p[(nt2 * 128 + nl) * 32 + kc * 16 + col];
        }
        __syncthreads();
#pragma unroll
        for (int ks = 0; ks < 2; ks++) {
            int r = warp * 16 + g, k0 = ks * 8 + tg;
            uint2 a[4] = {sZ[r][k0], sZ[r+8][k0], sZ[r][k0+4], sZ[r+8][k0+4]};
#pragma unroll
            for (int nt = 0; nt < 16; nt++) {
                int n = nt * 8 + g;
                uint2 bfr[2] = {sC[n][k0], sC[n][k0+4]};
                mma3v(c[nt], a, bfr);
            }
        }
    }
    float* orow = out + (size_t)bo * 65536;
#pragma unroll
    for (int nt = 0; nt < 16; nt++) {
        int h = mt2 * 128 + warp * 16 + g;
        int w = nt2 * 128 + nt * 8 + 2 * tg;
        *(float2*)&orow[(h)     * 256 + w] = make_float2(c[nt][0], c[nt][1]);
        *(float2*)&orow[(h + 8) * 256 + w] = make_float2(c[nt][2], c[nt][3]);
    }
}

extern "C" void kernel_launch(void* const* d_in, const int* in_sizes, int n_in,
                              void* d_out, int out_size) {
    const float* x   = (const float*)d_in[0];
    const float* wx1 = (const float*)d_in[1];
    const float* wx2 = (const float*)d_in[2];
    const float* wy  = (const float*)d_in[3];
    float* out = (float*)d_out;

    cudaFuncSetAttribute(k3a_mma, cudaFuncAttributeMaxDynamicSharedMemorySize, K3A_SMEM);
    cudaFuncSetAttribute(k3b_mma, cudaFuncAttributeMaxDynamicSharedMemorySize, K3B_SMEM);

    fill_all<<<128, 256>>>();
    fill_w<<<3072, 256>>>(wx1, wx2, wy);
    s1_wdft<<<2048, 256>>>(x);
    s2_hdft<<<256, 256>>>();
    k3a_mma<<<dim3(64, 4), 256, K3A_SMEM>>>();
    k3b_mma<<<dim3(32, 8), 256, K3B_SMEM>>>();
    s5_invh<<<dim3(2, 1024), 256>>>();
    s6_invw<<<dim3(2, 2, 1024), 256>>>(out);
}